// round 3
// baseline (speedup 1.0000x reference)
#include <cuda_runtime.h>
#include <math.h>

#define KNOTS   1024
#define SAMPLES 4096
#define S_PTS   4095
#define INV_SAMP (1.0f / 4096.0f)
#define NMOM 10
#define NBLK 32
#define NTHR 256

// ---------------- scratch (device globals; no allocation allowed) ------------
__device__ float g_smear[(size_t)KNOTS * S_PTS];   // general-fallback only
__device__ float g_A[KNOTS], g_B[KNOTS], g_cB[KNOTS], g_sin[KNOTS];
__device__ float g_erl[KNOTS], g_erh[KNOTS];
__device__ float g_v0[KNOTS];
__device__ int   g_cstk[KNOTS];
__device__ float g_clo[KNOTS], g_chi[KNOTS];
__device__ float g_glow[KNOTS], g_gd[KNOTS], g_grl[KNOTS], g_grh[KNOTS];
__device__ float g_rowsum[KNOTS], g_coef1[KNOTS], g_cw[KNOTS], g_w[KNOTS];
__device__ float g_envcoef[2 * NMOM];
__device__ float g_Rconst;
__device__ int   g_fastenv, g_anyvar;
__device__ unsigned g_count = 0;   // self-resetting per barrier episode
__device__ unsigned g_gen   = 0;   // monotone across replays

// ---------------- reductions --------------------------------------------------
__device__ __forceinline__ float warp_sum(float v) {
    #pragma unroll
    for (int o = 16; o > 0; o >>= 1) v += __shfl_xor_sync(0xFFFFFFFFu, v, o);
    return v;
}
__device__ __forceinline__ float block_sum(float v, float* sh) {
    int tid = threadIdx.x;
    v = warp_sum(v);
    if ((tid & 31) == 0) sh[tid >> 5] = v;
    __syncthreads();
    float r = 0.0f;
    if (tid < 32) {
        r = (tid < (NTHR >> 5)) ? sh[tid] : 0.0f;
        r = warp_sum(r);
    }
    __syncthreads();
    return r;  // valid in tid 0
}
__device__ __forceinline__ float block_max(float v, float* sh) {
    int tid = threadIdx.x;
    #pragma unroll
    for (int o = 16; o > 0; o >>= 1) v = fmaxf(v, __shfl_xor_sync(0xFFFFFFFFu, v, o));
    if ((tid & 31) == 0) sh[tid >> 5] = v;
    __syncthreads();
    float r = 0.0f;
    if (tid < 32) {
        r = (tid < (NTHR >> 5)) ? sh[tid] : 0.0f;
        #pragma unroll
        for (int o = 16; o > 0; o >>= 1) r = fmaxf(r, __shfl_xor_sync(0xFFFFFFFFu, r, o));
    }
    __syncthreads();
    return r;
}

// ---------------- software grid barrier (one wave; 32 co-resident blocks) ----
__device__ __forceinline__ void grid_sync() {
    __threadfence();              // release all this thread's global writes
    __syncthreads();
    if (threadIdx.x == 0) {
        unsigned my = *((volatile unsigned*)&g_gen);
        if (atomicAdd(&g_count, 1u) == NBLK - 1) {
            g_count = 0;
            __threadfence();
            *((volatile unsigned*)&g_gen) = my + 1;
        } else {
            while (*((volatile unsigned*)&g_gen) == my) { }
        }
        __threadfence();          // acquire
    }
    __syncthreads();
}

// ---------------- the one fused kernel ----------------------------------------
__global__ __launch_bounds__(NTHR, 1)
void knot_fused(const float* __restrict__ x,
                const float* __restrict__ sw,
                const float* __restrict__ kmean,
                const float* __restrict__ klow,
                const float* __restrict__ khigh,
                const float* __restrict__ emean,
                const float* __restrict__ elow,
                const float* __restrict__ ehigh,
                const float* __restrict__ pol,
                float* __restrict__ out) {
    __shared__ float sm[5 * KNOTS];   // 20 KB, aliased per phase
    __shared__ float red[32];

    const int tid = threadIdx.x;
    const int bid = blockIdx.x;
    const float lower = sw[0], upper = sw[1];

    // ===================== phase 1: per-knot params (blocks 0-3) =============
    if (bid < 4) {
        int k = bid * NTHR + tid;   // 0..1023
        float xk = x[k];
        float xlow  = (1.0f - lower) * xk;
        float xstep = ((upper - lower) * xk) * INV_SAMP;
        float rl = __expf(-klow[k]);
        float rh = __expf(-khigh[k]);
        float mean = kmean[k];

        float d  = xlow - mean;
        float r0 = (xlow <= mean) ? rl : rh;
        float a0 = d * r0;
        float v0 = __expf(-0.5f * a0 * a0);

        float sp, cp;
        __sincosf(pol[k], &sp, &cp);

        int cst = (xstep == 0.0f) ? 1 : 0;
        g_cstk[k] = cst;
        g_v0[k]   = v0;
        float B   = (float)S_PTS * v0;
        g_B[k]  = B;
        g_cB[k] = cp * B;
        g_sin[k] = sp;
        g_erl[k] = __expf(-elow[k]);
        g_erh[k] = __expf(-ehigh[k]);
        g_cw[k]  = 0.0f;
        if (cst) g_A[k] = B;   // A = S * v0 on constant rows

        // envelope params
        float lows  = xlow;
        float highs = (1.0f + upper) * xk;
        float erlw = __expf(-lows);
        float erhg = __expf(-highs);
        g_glow[k] = lows;  g_gd[k] = highs - lows;
        g_grl[k]  = erlw;  g_grh[k] = erhg;
        float hlo = xk * erlw, hhi = xk * erhg;
        g_clo[k] = 0.5f * hlo * hlo;
        g_chi[k] = 0.5f * hhi * hhi;

        // stash for in-block fallback row fill
        sm[tid]              = xlow;
        sm[256 + tid]        = xstep;
        sm[512 + tid]        = mean;
        sm[768 + tid]        = rl;
        sm[1024 + tid]       = rh;
        sm[1280 + tid]       = (float)cst;
        __syncthreads();

        // general fallback: materialize non-constant smear rows + A
        for (int kk = 0; kk < NTHR; kk++) {
            if (sm[1280 + kk] != 0.0f) continue;
            int krow = bid * NTHR + kk;
            float xl = sm[kk], xs = sm[256 + kk], mn = sm[512 + kk];
            float r1 = sm[768 + kk], r2 = sm[1024 + kk];
            float* __restrict__ row = &g_smear[(size_t)krow * S_PTS];
            float acc = 0.0f;
            for (int s = tid; s < S_PTS; s += NTHR) {
                float gv = fmaf(xs, (float)s, xl);
                float dd = gv - mn;
                float rr = (gv <= mn) ? r1 : r2;
                float aa = dd * rr;
                float vv = __expf(-0.5f * aa * aa);
                row[s] = vv;
                acc += vv;
            }
            float tot = block_sum(acc, red);
            if (tid == 0) g_A[krow] = tot;
        }
    }

    grid_sync();

    // ===================== phase 2: mix-matrix reductions ====================
    {
        float* sA   = sm;
        float* sEm  = sm + KNOTS;
        float* sErl = sm + 2 * KNOTS;
        float* sErh = sm + 3 * KNOTS;
        float* sCb  = sm + 4 * KNOTS;
        for (int t = tid; t < KNOTS; t += NTHR) {
            sA[t]   = g_A[t];
            sEm[t]  = emean[t];
            sErl[t] = g_erl[t];
            sErh[t] = g_erh[t];
            sCb[t]  = g_cB[t];
        }
        __syncthreads();

        int warp = tid >> 5, lane = tid & 31;
        #pragma unroll
        for (int rr = 0; rr < 4; rr++) {
            int i = bid * 32 + rr * 8 + warp;
            float AiS = sA[i] * (1.0f / (float)S_PTS);
            float Bi  = g_B[i];
            float rs = 0.0f, c1 = 0.0f;
            #pragma unroll 4
            for (int j = lane; j < KNOTS; j += 32) {
                float corr = AiS * sA[j];
                float em = sEm[j];
                float dd = corr - em;
                float r  = (corr <= em) ? sErl[j] : sErh[j];
                float a  = dd * r;
                float e  = 0.5f * a * a;
                if (e < 88.0f) {                 // beyond this exp underflows to 0
                    float m = __expf(-e);
                    if (j == i) m = 0.0f;
                    rs += m;
                    c1 += m * sCb[j];
                    float v = Bi * m;
                    if (v != 0.0f) atomicAdd(&g_cw[j], v);
                }
            }
            rs = warp_sum(rs);
            c1 = warp_sum(c1);
            if (lane == 0) { g_rowsum[i] = rs; g_coef1[i] = c1; }
        }
    }

    grid_sync();

    // ===================== phase 3: weights + moments (block 0) ==============
    if (bid == 0) {
        float clo4[4], chi4[4];
        float rc = 0.0f, nv = 0.0f, cm = 0.0f;
        #pragma unroll
        for (int q = 0; q < 4; q++) {
            int k = tid + q * NTHR;
            float w = g_coef1[k] + (float)(KNOTS - 1) - g_rowsum[k] + g_sin[k] * g_cw[k];
            g_w[k] = w;
            int c = g_cstk[k];
            if (c) rc += w * g_v0[k]; else nv += 1.0f;
            clo4[q] = g_clo[k]; chi4[q] = g_chi[k];
            cm = fmaxf(cm, fmaxf(clo4[q], chi4[q]));
        }
        float Rc   = block_sum(rc, red);
        float Anyv = block_sum(nv, red);
        float Cmax = block_max(cm, red);

        const float invfact[NMOM] = {1.0f, 1.0f, 0.5f, 1.0f/6.0f, 1.0f/24.0f, 1.0f/120.0f,
                                     1.0f/720.0f, 1.0f/5040.0f, 1.0f/40320.0f, 1.0f/362880.0f};
        float pl4[4] = {1,1,1,1}, ph4[4] = {1,1,1,1};
        #pragma unroll
        for (int n = 1; n < NMOM; n++) {
            float sl = 0.0f, sh2 = 0.0f;
            #pragma unroll
            for (int q = 0; q < 4; q++) {
                pl4[q] *= clo4[q]; ph4[q] *= chi4[q];
                sl += pl4[q]; sh2 += ph4[q];
            }
            float Ml = block_sum(sl, red);
            float Mh = block_sum(sh2, red);
            if (tid == 0) {
                g_envcoef[n]        = Ml * invfact[n];
                g_envcoef[NMOM + n] = Mh * invfact[n];
            }
        }
        if (tid == 0) {
            g_envcoef[0]    = (float)KNOTS;
            g_envcoef[NMOM] = (float)KNOTS;
            g_Rconst = Rc;
            g_anyvar = (Anyv > 0.0f) ? 1 : 0;
            float phi0 = -lower;
            float phiE = fmaf((float)(S_PTS - 1) * INV_SAMP, lower + upper, -lower);
            float tmax = fmaxf(phi0 * phi0, phiE * phiE);
            float gate = Cmax * tmax;
            g_fastenv = (gate <= 1.0f) ? 1 : 0;   // NaN -> slow path
        }
    }

    grid_sync();

    // ===================== phase 4: output ===================================
    {
        int s = bid * NTHR + tid;
        if (s < S_PTS) {
            float xi  = (float)s * INV_SAMP;
            float phi = fmaf(xi, lower + upper, -lower);
            int side  = (phi <= 0.0f) ? 0 : 1;
            float t   = phi * phi;

            float env;
            if (g_fastenv) {
                const float* cf = g_envcoef + side * NMOM;
                float u = -t;
                env = cf[NMOM - 1];
                #pragma unroll
                for (int n = NMOM - 2; n >= 0; n--) env = fmaf(env, u, cf[n]);
            } else {
                env = 0.0f;
                for (int k = 0; k < KNOTS; k++) {
                    float mean = x[k];
                    float gv = fmaf(g_gd[k], xi, g_glow[k]);
                    float dd = gv - mean;
                    float r  = (gv <= mean) ? g_grl[k] : g_grh[k];
                    float a  = dd * r;
                    env += __expf(-0.5f * a * a);
                }
            }

            float res = g_Rconst;
            if (g_anyvar) {
                for (int k = 0; k < KNOTS; k++) {
                    if (g_cstk[k] == 0)
                        res = fmaf(g_w[k], g_smear[(size_t)k * S_PTS + s], res);
                }
            }
            out[s] = env * res;
        }
    }
}

// ---------------- launch ------------------------------------------------------
extern "C" void kernel_launch(void* const* d_in, const int* in_sizes, int n_in,
                              void* d_out, int out_size) {
    const float* x     = (const float*)d_in[0];
    const float* sw    = (const float*)d_in[1];
    const float* kmean = (const float*)d_in[2];
    const float* klow  = (const float*)d_in[3];
    const float* khigh = (const float*)d_in[4];
    const float* emean = (const float*)d_in[5];
    const float* elow  = (const float*)d_in[6];
    const float* ehigh = (const float*)d_in[7];
    const float* pol   = (const float*)d_in[8];
    float* out = (float*)d_out;

    knot_fused<<<NBLK, NTHR>>>(x, sw, kmean, klow, khigh, emean, elow, ehigh, pol, out);
}

// round 4
// speedup vs baseline: 1.3101x; 1.3101x over previous
#include <cuda_runtime.h>
#include <math.h>

#define KNOTS   1024
#define SAMPLES 4096
#define S_PTS   4095
#define INV_SAMP (1.0f / 4096.0f)
#define NMOM 10
#define NBLK1 32
#define NBLK2 16
#define NTHR  256

// ---------------- scratch (device globals; no allocation allowed) ------------
__device__ float g_smear[(size_t)KNOTS * S_PTS];          // general-fallback only
__device__ float g_rowsum[KNOTS], g_coef1[KNOTS];
__device__ float g_cwp[NBLK1 * KNOTS];                    // per-block cw partials

// ---------------- reductions --------------------------------------------------
__device__ __forceinline__ float warp_sum(float v) {
    #pragma unroll
    for (int o = 16; o > 0; o >>= 1) v += __shfl_xor_sync(0xFFFFFFFFu, v, o);
    return v;
}
__device__ __forceinline__ float block_sum(float v, float* sh) {
    int tid = threadIdx.x;
    v = warp_sum(v);
    if ((tid & 31) == 0) sh[tid >> 5] = v;
    __syncthreads();
    float r = 0.0f;
    if (tid < 32) {
        r = (tid < (NTHR >> 5)) ? sh[tid] : 0.0f;
        r = warp_sum(r);
    }
    __syncthreads();
    return r;  // valid in tid 0
}
__device__ __forceinline__ float block_max(float v, float* sh) {
    int tid = threadIdx.x;
    #pragma unroll
    for (int o = 16; o > 0; o >>= 1) v = fmaxf(v, __shfl_xor_sync(0xFFFFFFFFu, v, o));
    if ((tid & 31) == 0) sh[tid >> 5] = v;
    __syncthreads();
    float r = 0.0f;
    if (tid < 32) {
        r = (tid < (NTHR >> 5)) ? sh[tid] : 0.0f;
        #pragma unroll
        for (int o = 16; o > 0; o >>= 1) r = fmaxf(r, __shfl_xor_sync(0xFFFFFFFFu, r, o));
    }
    __syncthreads();
    return r;
}

// ======================= K1: redundant params + mix ===========================
__global__ __launch_bounds__(NTHR, 1)
void k1_mix(const float* __restrict__ x,
            const float* __restrict__ sw,
            const float* __restrict__ kmean,
            const float* __restrict__ klow,
            const float* __restrict__ khigh,
            const float* __restrict__ emean,
            const float* __restrict__ elow,
            const float* __restrict__ ehigh,
            const float* __restrict__ pol) {
    __shared__ float sA[KNOTS], sB[KNOTS], sCb[KNOTS], sEm[KNOTS];
    __shared__ float sErl[KNOTS], sErh[KNOTS], sXs[KNOTS], sCw[KNOTS];
    __shared__ float red[32];
    __shared__ int s_nvar;

    const int tid = threadIdx.x;
    const int bid = blockIdx.x;
    const float lower = sw[0], upper = sw[1];

    if (tid == 0) s_nvar = 0;

    // ---- redundant per-knot params (4 knots/thread) ----
    #pragma unroll
    for (int q = 0; q < 4; q++) {
        int k = tid + q * NTHR;
        float xk = x[k];
        float xlow  = (1.0f - lower) * xk;
        float xstep = ((upper - lower) * xk) * INV_SAMP;
        float rl = __expf(-klow[k]);
        float rh = __expf(-khigh[k]);
        float mean = kmean[k];
        float d  = xlow - mean;
        float r0 = (xlow <= mean) ? rl : rh;
        float a0 = d * r0;
        float v0 = __expf(-0.5f * a0 * a0);
        float B  = (float)S_PTS * v0;
        sB[k]  = B;
        sA[k]  = B;                       // fast-path A (overwritten on fallback)
        sCb[k] = __cosf(pol[k]) * B;
        sEm[k] = emean[k];
        sErl[k] = __expf(-elow[k]);
        sErh[k] = __expf(-ehigh[k]);
        sXs[k] = xstep;
        sCw[k] = 0.0f;
        if (xstep != 0.0f) atomicAdd(&s_nvar, 1);
    }
    __syncthreads();

    // ---- general fallback: A via S-loop, owning block materializes rows ----
    if (s_nvar > 0) {
        for (int k = 0; k < KNOTS; k++) {
            if (sXs[k] == 0.0f) continue;
            float xk = x[k];
            float xlow  = (1.0f - lower) * xk;
            float xstep = ((upper - lower) * xk) * INV_SAMP;
            float rl = __expf(-klow[k]);
            float rh = __expf(-khigh[k]);
            float mean = kmean[k];
            bool own = (bid == (k >> 5));
            float* __restrict__ row = &g_smear[(size_t)k * S_PTS];
            float acc = 0.0f;
            for (int s = tid; s < S_PTS; s += NTHR) {
                float gv = fmaf(xstep, (float)s, xlow);
                float dd = gv - mean;
                float rr = (gv <= mean) ? rl : rh;
                float aa = dd * rr;
                float vv = __expf(-0.5f * aa * aa);
                if (own) row[s] = vv;
                acc += vv;
            }
            float tot = block_sum(acc, red);
            if (tid == 0) sA[k] = tot;
            __syncthreads();
        }
    }

    // ---- mix rows: 32 rows per block, 8 warps x 4 rows ----
    int warp = tid >> 5, lane = tid & 31;
    #pragma unroll
    for (int rr = 0; rr < 4; rr++) {
        int i = bid * 32 + rr * 8 + warp;
        float AiS = sA[i] * (1.0f / (float)S_PTS);
        float Bi  = sB[i];
        float rs = 0.0f, c1 = 0.0f;
        #pragma unroll 4
        for (int j = lane; j < KNOTS; j += 32) {
            float corr = AiS * sA[j];
            float em = sEm[j];
            float dd = corr - em;
            float r  = (corr <= em) ? sErl[j] : sErh[j];
            float a  = dd * r;
            float e  = 0.5f * a * a;
            if (e < 88.0f) {                  // beyond this exp underflows to 0
                float m = __expf(-e);
                if (j == i) m = 0.0f;
                rs += m;
                c1 += m * sCb[j];
                float v = Bi * m;
                if (v != 0.0f) atomicAdd(&sCw[j], v);
            }
        }
        rs = warp_sum(rs);
        c1 = warp_sum(c1);
        if (lane == 0) { g_rowsum[i] = rs; g_coef1[i] = c1; }
    }
    __syncthreads();

    // ---- write cw partial (fully rewritten each run: no stale-replay state) --
    #pragma unroll
    for (int q = 0; q < 4; q++) {
        int k = tid + q * NTHR;
        g_cwp[bid * KNOTS + k] = sCw[k];
    }
}

// ======================= K2: weights + moments + output =======================
__global__ __launch_bounds__(NTHR, 1)
void k2_out(const float* __restrict__ x,
            const float* __restrict__ sw,
            const float* __restrict__ kmean,
            const float* __restrict__ klow,
            const float* __restrict__ khigh,
            const float* __restrict__ pol,
            float* __restrict__ out) {
    __shared__ float s_w[KNOTS], s_glow[KNOTS], s_gd[KNOTS];
    __shared__ float s_grl[KNOTS], s_grh[KNOTS], s_cst[KNOTS];
    __shared__ float s_cf[2 * NMOM];
    __shared__ float red[32];
    __shared__ float s_R;
    __shared__ int s_fastenv, s_anyvar;

    const int tid = threadIdx.x;
    const int bid = blockIdx.x;
    const float lower = sw[0], upper = sw[1];

    float clo4[4], chi4[4];
    float rc = 0.0f, nv = 0.0f, cm = 0.0f;

    #pragma unroll
    for (int q = 0; q < 4; q++) {
        int k = tid + q * NTHR;
        float xk = x[k];
        float xlow  = (1.0f - lower) * xk;
        float xstep = ((upper - lower) * xk) * INV_SAMP;
        int cst = (xstep == 0.0f) ? 1 : 0;

        // v0 (smear at s=0)
        float rl = __expf(-klow[k]);
        float rh = __expf(-khigh[k]);
        float mean = kmean[k];
        float d  = xlow - mean;
        float r0 = (xlow <= mean) ? rl : rh;
        float a0 = d * r0;
        float v0 = __expf(-0.5f * a0 * a0);

        // cw = sum of 32 block partials
        float cw = 0.0f;
        #pragma unroll 8
        for (int p = 0; p < NBLK1; p++) cw += g_cwp[p * KNOTS + k];

        float w = g_coef1[k] + (float)(KNOTS - 1) - g_rowsum[k]
                + __sinf(pol[k]) * cw;
        s_w[k]   = w;
        s_cst[k] = (float)cst;
        if (cst) rc += w * v0; else nv += 1.0f;

        // envelope params
        float lows  = xlow;
        float highs = (1.0f + upper) * xk;
        float erlw = __expf(-lows);
        float erhg = __expf(-highs);
        s_glow[k] = lows;  s_gd[k] = highs - lows;
        s_grl[k]  = erlw;  s_grh[k] = erhg;
        float hlo = xk * erlw, hhi = xk * erhg;
        float clo = 0.5f * hlo * hlo;
        float chi = 0.5f * hhi * hhi;
        clo4[q] = clo; chi4[q] = chi;
        cm = fmaxf(cm, fmaxf(clo, chi));
    }

    float Rc   = block_sum(rc, red);
    float Anyv = block_sum(nv, red);
    float Cmax = block_max(cm, red);

    const float invfact[NMOM] = {1.0f, 1.0f, 0.5f, 1.0f/6.0f, 1.0f/24.0f, 1.0f/120.0f,
                                 1.0f/720.0f, 1.0f/5040.0f, 1.0f/40320.0f, 1.0f/362880.0f};
    float pl4[4] = {1,1,1,1}, ph4[4] = {1,1,1,1};
    #pragma unroll
    for (int n = 1; n < NMOM; n++) {
        float sl = 0.0f, sh2 = 0.0f;
        #pragma unroll
        for (int q = 0; q < 4; q++) {
            pl4[q] *= clo4[q]; ph4[q] *= chi4[q];
            sl += pl4[q]; sh2 += ph4[q];
        }
        float Ml = block_sum(sl, red);
        float Mh = block_sum(sh2, red);
        if (tid == 0) {
            s_cf[n]        = Ml * invfact[n];
            s_cf[NMOM + n] = Mh * invfact[n];
        }
    }
    if (tid == 0) {
        s_cf[0]    = (float)KNOTS;
        s_cf[NMOM] = (float)KNOTS;
        s_R = Rc;
        s_anyvar = (Anyv > 0.0f) ? 1 : 0;
        float phi0 = -lower;
        float phiE = fmaf((float)(S_PTS - 1) * INV_SAMP, lower + upper, -lower);
        float tmax = fmaxf(phi0 * phi0, phiE * phiE);
        float gate = Cmax * tmax;
        s_fastenv = (gate <= 1.0f) ? 1 : 0;   // NaN -> slow path
    }
    __syncthreads();

    // ---- output: one sample per thread ----
    int s = bid * NTHR + tid;
    if (s >= S_PTS) return;

    float xi  = (float)s * INV_SAMP;
    float phi = fmaf(xi, lower + upper, -lower);
    int side  = (phi <= 0.0f) ? 0 : 1;
    float t   = phi * phi;

    float env;
    if (s_fastenv) {
        const float* cf = s_cf + side * NMOM;
        float u = -t;
        env = cf[NMOM - 1];
        #pragma unroll
        for (int n = NMOM - 2; n >= 0; n--) env = fmaf(env, u, cf[n]);
    } else {
        env = 0.0f;
        for (int k = 0; k < KNOTS; k++) {
            float mean = x[k];
            float gv = fmaf(s_gd[k], xi, s_glow[k]);
            float dd = gv - mean;
            float r  = (gv <= mean) ? s_grl[k] : s_grh[k];
            float a  = dd * r;
            env += __expf(-0.5f * a * a);
        }
    }

    float res = s_R;
    if (s_anyvar) {
        for (int k = 0; k < KNOTS; k++) {
            if (s_cst[k] == 0.0f)
                res = fmaf(s_w[k], g_smear[(size_t)k * S_PTS + s], res);
        }
    }
    out[s] = env * res;
}

// ---------------- launch ------------------------------------------------------
extern "C" void kernel_launch(void* const* d_in, const int* in_sizes, int n_in,
                              void* d_out, int out_size) {
    const float* x     = (const float*)d_in[0];
    const float* sw    = (const float*)d_in[1];
    const float* kmean = (const float*)d_in[2];
    const float* klow  = (const float*)d_in[3];
    const float* khigh = (const float*)d_in[4];
    const float* emean = (const float*)d_in[5];
    const float* elow  = (const float*)d_in[6];
    const float* ehigh = (const float*)d_in[7];
    const float* pol   = (const float*)d_in[8];
    float* out = (float*)d_out;

    k1_mix<<<NBLK1, NTHR>>>(x, sw, kmean, klow, khigh, emean, elow, ehigh, pol);
    k2_out<<<NBLK2, NTHR>>>(x, sw, kmean, klow, khigh, pol, out);
}

// round 5
// speedup vs baseline: 2.0728x; 1.5821x over previous
#include <cuda_runtime.h>
#include <math.h>

#define KNOTS   1024
#define SAMPLES 4096
#define S_PTS   4095
#define INV_SAMP (1.0f / 4096.0f)
#define NMOM  10
#define NMIX  32          // mix blocks
#define NBLK1 (NMIX + 1)  // + stats block
#define NBLK2 16
#define NTHR  256
#define NQ    21          // batched-reduction quantity count

// ---------------- scratch (device globals; no allocation allowed) ------------
__device__ float g_smear[(size_t)KNOTS * S_PTS];          // general-fallback only
__device__ float g_rowsum[KNOTS], g_coef1[KNOTS];
__device__ float g_cwp[NMIX * KNOTS];                     // fallback cw partials
__device__ float g_Rp[NMIX];                              // Rconst partials
__device__ float g_envcoef[2 * NMOM];
__device__ float g_Rbase;
__device__ int   g_fastenv, g_anyvar;

// ---------------- reductions --------------------------------------------------
__device__ __forceinline__ float warp_sum(float v) {
    #pragma unroll
    for (int o = 16; o > 0; o >>= 1) v += __shfl_xor_sync(0xFFFFFFFFu, v, o);
    return v;
}
__device__ __forceinline__ float warp_max(float v) {
    #pragma unroll
    for (int o = 16; o > 0; o >>= 1) v = fmaxf(v, __shfl_xor_sync(0xFFFFFFFFu, v, o));
    return v;
}
__device__ __forceinline__ float block_sum(float v, float* sh) {
    int tid = threadIdx.x;
    v = warp_sum(v);
    if ((tid & 31) == 0) sh[tid >> 5] = v;
    __syncthreads();
    float r = 0.0f;
    if (tid < 32) {
        r = (tid < (NTHR >> 5)) ? sh[tid] : 0.0f;
        r = warp_sum(r);
    }
    __syncthreads();
    return r;  // valid in tid 0
}

// ======================= K1: mix + scalar partials + stats ====================
__global__ __launch_bounds__(NTHR, 1)
void k1_mix(const float* __restrict__ x,
            const float* __restrict__ sw,
            const float* __restrict__ kmean,
            const float* __restrict__ klow,
            const float* __restrict__ khigh,
            const float* __restrict__ emean,
            const float* __restrict__ elow,
            const float* __restrict__ ehigh,
            const float* __restrict__ pol) {
    const int tid = threadIdx.x;
    const int bid = blockIdx.x;
    const float lower = sw[0], upper = sw[1];

    // ---------------- stats block: moments + gate + Rbase --------------------
    if (bid == NMIX) {
        __shared__ float buf[NQ * NTHR];   // 21 KB transpose buffer
        __shared__ float res[NQ];

        float pl4[4], ph4[4], v0s = 0.0f, nv = 0.0f, cm = 0.0f;
        float plp[4] = {1,1,1,1}, php[4] = {1,1,1,1};
        float clo4[4], chi4[4];
        #pragma unroll
        for (int q = 0; q < 4; q++) {
            int k = tid + q * NTHR;
            float xk = x[k];
            float xlow  = (1.0f - lower) * xk;
            float xstep = ((upper - lower) * xk) * INV_SAMP;
            int cst = (xstep == 0.0f) ? 1 : 0;
            float rl = __expf(-klow[k]);
            float rh = __expf(-khigh[k]);
            float mean = kmean[k];
            float d  = xlow - mean;
            float r0 = (xlow <= mean) ? rl : rh;
            float a0 = d * r0;
            float v0 = __expf(-0.5f * a0 * a0);
            if (cst) v0s += v0; else nv += 1.0f;

            float highs = (1.0f + upper) * xk;
            float hlo = xk * __expf(-xlow);
            float hhi = xk * __expf(-highs);
            clo4[q] = 0.5f * hlo * hlo;
            chi4[q] = 0.5f * hhi * hhi;
            cm = fmaxf(cm, fmaxf(clo4[q], chi4[q]));
        }
        (void)pl4; (void)ph4;
        // per-thread moment partials n = 1..9
        #pragma unroll
        for (int n = 1; n < NMOM; n++) {
            float sl = 0.0f, sh2 = 0.0f;
            #pragma unroll
            for (int q = 0; q < 4; q++) {
                plp[q] *= clo4[q]; php[q] *= chi4[q];
                sl += plp[q]; sh2 += php[q];
            }
            buf[(n - 1) * NTHR + tid]     = sl;   // q 0..8  : low moments
            buf[(8 + n) * NTHR + tid]     = sh2;  // q 9..17 : high moments
        }
        buf[18 * NTHR + tid] = v0s;   // q18: sum v0 (const knots)
        buf[19 * NTHR + tid] = nv;    // q19: nonconst count
        buf[20 * NTHR + tid] = cm;    // q20: max c (max-reduce)
        __syncthreads();

        int warp = tid >> 5, lane = tid & 31;
        for (int q = warp; q < NQ; q += 8) {
            const float* b = buf + q * NTHR;
            if (q == 20) {
                float m = fmaxf(fmaxf(b[lane], b[lane + 32]),
                         fmaxf(fmaxf(b[lane + 64],  b[lane + 96]),
                         fmaxf(fmaxf(b[lane + 128], b[lane + 160]),
                               fmaxf(b[lane + 192], b[lane + 224]))));
                m = warp_max(m);
                if (lane == 0) res[q] = m;
            } else {
                float s = b[lane] + b[lane + 32] + b[lane + 64] + b[lane + 96]
                        + b[lane + 128] + b[lane + 160] + b[lane + 192] + b[lane + 224];
                s = warp_sum(s);
                if (lane == 0) res[q] = s;
            }
        }
        __syncthreads();

        if (tid == 0) {
            const float invfact[NMOM] = {1.0f, 1.0f, 0.5f, 1.0f/6.0f, 1.0f/24.0f, 1.0f/120.0f,
                                         1.0f/720.0f, 1.0f/5040.0f, 1.0f/40320.0f, 1.0f/362880.0f};
            g_envcoef[0]    = (float)KNOTS;
            g_envcoef[NMOM] = (float)KNOTS;
            #pragma unroll
            for (int n = 1; n < NMOM; n++) {
                g_envcoef[n]        = res[n - 1] * invfact[n];
                g_envcoef[NMOM + n] = res[8 + n] * invfact[n];
            }
            g_Rbase  = (float)(KNOTS - 1) * res[18];
            g_anyvar = (res[19] > 0.0f) ? 1 : 0;
            float phi0 = -lower;
            float phiE = fmaf((float)(S_PTS - 1) * INV_SAMP, lower + upper, -lower);
            float tmax = fmaxf(phi0 * phi0, phiE * phiE);
            float gate = res[20] * tmax;
            g_fastenv = (gate <= 1.0f) ? 1 : 0;   // NaN -> slow path
        }
        return;
    }

    // ---------------- mix blocks ---------------------------------------------
    __shared__ float sA[KNOTS], sB[KNOTS], sV0c[KNOTS], sSvj[KNOTS];
    __shared__ float sCb[KNOTS], sEm[KNOTS], sErl[KNOTS], sErh[KNOTS];
    __shared__ float sXs[KNOTS], sCw[KNOTS];
    __shared__ float red[32];
    __shared__ int s_nvar;

    if (tid == 0) s_nvar = 0;

    #pragma unroll
    for (int q = 0; q < 4; q++) {
        int k = tid + q * NTHR;
        float xk = x[k];
        float xlow  = (1.0f - lower) * xk;
        float xstep = ((upper - lower) * xk) * INV_SAMP;
        float rl = __expf(-klow[k]);
        float rh = __expf(-khigh[k]);
        float mean = kmean[k];
        float d  = xlow - mean;
        float r0 = (xlow <= mean) ? rl : rh;
        float a0 = d * r0;
        float v0 = __expf(-0.5f * a0 * a0);
        float B  = (float)S_PTS * v0;
        int cst = (xstep == 0.0f) ? 1 : 0;
        float v0c = cst ? v0 : 0.0f;
        float sp, cp;
        __sincosf(pol[k], &sp, &cp);

        sA[k]   = B;                 // fast-path A (overwritten on fallback)
        sB[k]   = B;
        sV0c[k] = v0c;
        sSvj[k] = sp * v0c;
        sCb[k]  = cp * B;
        sEm[k]  = emean[k];
        sErl[k] = __expf(-elow[k]);
        sErh[k] = __expf(-ehigh[k]);
        sXs[k]  = xstep;
        sCw[k]  = 0.0f;
        if (!cst) atomicAdd(&s_nvar, 1);
    }
    __syncthreads();

    // general fallback: recompute A; owning block materializes smear rows
    if (s_nvar > 0) {
        for (int k = 0; k < KNOTS; k++) {
            if (sXs[k] == 0.0f) continue;
            float xk = x[k];
            float xlow  = (1.0f - lower) * xk;
            float xstep = ((upper - lower) * xk) * INV_SAMP;
            float rl = __expf(-klow[k]);
            float rh = __expf(-khigh[k]);
            float mean = kmean[k];
            bool own = (bid == (k >> 5));
            float* __restrict__ row = &g_smear[(size_t)k * S_PTS];
            float acc = 0.0f;
            for (int s = tid; s < S_PTS; s += NTHR) {
                float gv = fmaf(xstep, (float)s, xlow);
                float dd = gv - mean;
                float rr = (gv <= mean) ? rl : rh;
                float aa = dd * rr;
                float vv = __expf(-0.5f * aa * aa);
                if (own) row[s] = vv;
                acc += vv;
            }
            float tot = block_sum(acc, red);
            if (tid == 0) sA[k] = tot;
            __syncthreads();
        }
    }

    // mix rows: 32 per block = 8 warps x 4 rows; accumulate Rconst partial
    int warp = tid >> 5, lane = tid & 31;
    float rp = 0.0f;
    #pragma unroll
    for (int rr = 0; rr < 4; rr++) {
        int i = bid * 32 + rr * 8 + warp;
        float AiS  = sA[i] * (1.0f / (float)S_PTS);
        float Bi   = sB[i];
        float v0ci = sV0c[i];
        float rs = 0.0f, c1 = 0.0f;
        #pragma unroll 4
        for (int j = lane; j < KNOTS; j += 32) {
            float corr = AiS * sA[j];
            float em = sEm[j];
            float dd = corr - em;
            float r  = (corr <= em) ? sErl[j] : sErh[j];
            float a  = dd * r;
            float e  = 0.5f * a * a;
            if (e < 88.0f) {                  // beyond this exp underflows to 0
                float m = __expf(-e);
                if (j == i) m = 0.0f;
                float cb = sCb[j];
                rs += m;
                c1 += m * cb;
                rp += m * (v0ci * (cb - 1.0f) + Bi * sSvj[j]);
                float v = Bi * m;
                if (v != 0.0f) atomicAdd(&sCw[j], v);
            }
        }
        rs = warp_sum(rs);
        c1 = warp_sum(c1);
        if (lane == 0) { g_rowsum[i] = rs; g_coef1[i] = c1; }
    }
    float rpt = block_sum(rp, red);
    if (tid == 0) g_Rp[bid] = rpt;
    __syncthreads();

    // fallback cw partials (fully rewritten each run)
    #pragma unroll
    for (int q = 0; q < 4; q++) {
        int k = tid + q * NTHR;
        g_cwp[bid * KNOTS + k] = sCw[k];
    }
}

// ======================= K2: output ===========================================
__global__ __launch_bounds__(NTHR, 1)
void k2_out(const float* __restrict__ x,
            const float* __restrict__ sw,
            const float* __restrict__ kmean,
            const float* __restrict__ klow,
            const float* __restrict__ khigh,
            const float* __restrict__ pol,
            float* __restrict__ out) {
    __shared__ float s_w[KNOTS], s_glow[KNOTS], s_gd[KNOTS];
    __shared__ float s_grl[KNOTS], s_grh[KNOTS], s_cst[KNOTS];

    const int tid = threadIdx.x;
    const int bid = blockIdx.x;
    const float lower = sw[0], upper = sw[1];

    const int anyvar  = g_anyvar;
    const int fastenv = g_fastenv;

    // R = Rbase + sum of 32 partials (broadcast loads)
    float R = g_Rbase;
    #pragma unroll
    for (int p = 0; p < NMIX; p++) R += g_Rp[p];

    // fallback: per-knot weights + envelope params (only if any nonconst knot)
    if (anyvar) {
        #pragma unroll
        for (int q = 0; q < 4; q++) {
            int k = tid + q * NTHR;
            float xk = x[k];
            float xlow  = (1.0f - lower) * xk;
            float xstep = ((upper - lower) * xk) * INV_SAMP;
            int cst = (xstep == 0.0f) ? 1 : 0;
            float cw = 0.0f;
            #pragma unroll 8
            for (int p = 0; p < NMIX; p++) cw += g_cwp[p * KNOTS + k];
            float w = g_coef1[k] + (float)(KNOTS - 1) - g_rowsum[k]
                    + __sinf(pol[k]) * cw;
            s_w[k]   = w;
            s_cst[k] = (float)cst;
            float highs = (1.0f + upper) * xk;
            s_glow[k] = xlow;  s_gd[k] = highs - xlow;
            s_grl[k]  = __expf(-xlow);
            s_grh[k]  = __expf(-highs);
        }
        __syncthreads();
    }

    int s = bid * NTHR + tid;
    if (s >= S_PTS) return;

    float xi  = (float)s * INV_SAMP;
    float phi = fmaf(xi, lower + upper, -lower);
    float t   = phi * phi;

    float env;
    if (fastenv) {
        const float* cf = g_envcoef + ((phi <= 0.0f) ? 0 : NMOM);
        float u = -t;
        env = cf[NMOM - 1];
        #pragma unroll
        for (int n = NMOM - 2; n >= 0; n--) env = fmaf(env, u, cf[n]);
    } else {
        env = 0.0f;
        for (int k = 0; k < KNOTS; k++) {
            float mean = x[k];
            float gv = fmaf(s_gd[k], xi, s_glow[k]);
            float dd = gv - mean;
            float r  = (gv <= mean) ? s_grl[k] : s_grh[k];
            float a  = dd * r;
            env += __expf(-0.5f * a * a);
        }
    }

    float res = R;
    if (anyvar) {
        for (int k = 0; k < KNOTS; k++) {
            if (s_cst[k] == 0.0f)
                res = fmaf(s_w[k], g_smear[(size_t)k * S_PTS + s], res);
        }
    }
    out[s] = env * res;
}

// ---------------- launch ------------------------------------------------------
extern "C" void kernel_launch(void* const* d_in, const int* in_sizes, int n_in,
                              void* d_out, int out_size) {
    const float* x     = (const float*)d_in[0];
    const float* sw    = (const float*)d_in[1];
    const float* kmean = (const float*)d_in[2];
    const float* klow  = (const float*)d_in[3];
    const float* khigh = (const float*)d_in[4];
    const float* emean = (const float*)d_in[5];
    const float* elow  = (const float*)d_in[6];
    const float* ehigh = (const float*)d_in[7];
    const float* pol   = (const float*)d_in[8];
    float* out = (float*)d_out;

    k1_mix<<<NBLK1, NTHR>>>(x, sw, kmean, klow, khigh, emean, elow, ehigh, pol);
    k2_out<<<NBLK2, NTHR>>>(x, sw, kmean, klow, khigh, pol, out);
}

// round 6
// speedup vs baseline: 3.3164x; 1.6000x over previous
#include <cuda_runtime.h>
#include <math.h>

#define KNOTS   1024
#define SAMPLES 4096
#define S_PTS   4095
#define INV_SAMP (1.0f / 4096.0f)
#define NMOM  10
#define NMIX  128         // mix blocks (8 rows each)
#define NBLK1 (NMIX + 1)  // + stats block
#define NBLK2 16
#define NTHR  256
#define NQ    21          // batched stats-reduction quantity count

// ---------------- scratch (device globals; no allocation allowed) ------------
__device__ float g_smear[(size_t)KNOTS * S_PTS];          // general-fallback only
__device__ float g_rowsum[KNOTS], g_coef1[KNOTS];
__device__ float g_cwp[NMIX * KNOTS];                     // fallback cw partials
__device__ float g_Rp[NMIX];                              // Rconst partials
__device__ float g_envcoef[2 * NMOM];
__device__ float g_Rbase;
__device__ int   g_fastenv, g_anyvar;

// ---------------- reductions --------------------------------------------------
__device__ __forceinline__ float warp_sum(float v) {
    #pragma unroll
    for (int o = 16; o > 0; o >>= 1) v += __shfl_xor_sync(0xFFFFFFFFu, v, o);
    return v;
}
__device__ __forceinline__ float warp_max(float v) {
    #pragma unroll
    for (int o = 16; o > 0; o >>= 1) v = fmaxf(v, __shfl_xor_sync(0xFFFFFFFFu, v, o));
    return v;
}
__device__ __forceinline__ float block_sum(float v, float* sh) {
    int tid = threadIdx.x;
    v = warp_sum(v);
    if ((tid & 31) == 0) sh[tid >> 5] = v;
    __syncthreads();
    float r = 0.0f;
    if (tid < 32) {
        r = (tid < (NTHR >> 5)) ? sh[tid] : 0.0f;
        r = warp_sum(r);
    }
    __syncthreads();
    return r;  // valid in tid 0
}

// ======================= K1: mix + scalar partials + stats ====================
__global__ __launch_bounds__(NTHR, 1)
void k1_mix(const float* __restrict__ x,
            const float* __restrict__ sw,
            const float* __restrict__ kmean,
            const float* __restrict__ klow,
            const float* __restrict__ khigh,
            const float* __restrict__ emean,
            const float* __restrict__ elow,
            const float* __restrict__ ehigh,
            const float* __restrict__ pol) {
    const int tid = threadIdx.x;
    const int bid = blockIdx.x;
    const float lower = sw[0], upper = sw[1];

    // ---------------- stats block: moments + gate + Rbase --------------------
    if (bid == NMIX) {
        __shared__ float buf[NQ * NTHR];
        __shared__ float res[NQ];

        float v0s = 0.0f, nv = 0.0f, cm = 0.0f;
        float plp[4] = {1,1,1,1}, php[4] = {1,1,1,1};
        float clo4[4], chi4[4];
        #pragma unroll
        for (int q = 0; q < 4; q++) {
            int k = tid + q * NTHR;
            float xk = x[k];
            float xlow  = (1.0f - lower) * xk;
            float xstep = ((upper - lower) * xk) * INV_SAMP;
            int cst = (xstep == 0.0f) ? 1 : 0;
            float rl = __expf(-klow[k]);
            float rh = __expf(-khigh[k]);
            float mean = kmean[k];
            float d  = xlow - mean;
            float r0 = (xlow <= mean) ? rl : rh;
            float a0 = d * r0;
            float v0 = __expf(-0.5f * a0 * a0);
            if (cst) v0s += v0; else nv += 1.0f;

            float highs = (1.0f + upper) * xk;
            float hlo = xk * __expf(-xlow);
            float hhi = xk * __expf(-highs);
            clo4[q] = 0.5f * hlo * hlo;
            chi4[q] = 0.5f * hhi * hhi;
            cm = fmaxf(cm, fmaxf(clo4[q], chi4[q]));
        }
        #pragma unroll
        for (int n = 1; n < NMOM; n++) {
            float sl = 0.0f, sh2 = 0.0f;
            #pragma unroll
            for (int q = 0; q < 4; q++) {
                plp[q] *= clo4[q]; php[q] *= chi4[q];
                sl += plp[q]; sh2 += php[q];
            }
            buf[(n - 1) * NTHR + tid] = sl;    // q 0..8  : low moments
            buf[(8 + n) * NTHR + tid] = sh2;   // q 9..17 : high moments
        }
        buf[18 * NTHR + tid] = v0s;
        buf[19 * NTHR + tid] = nv;
        buf[20 * NTHR + tid] = cm;
        __syncthreads();

        int warp = tid >> 5, lane = tid & 31;
        for (int q = warp; q < NQ; q += 8) {
            const float* b = buf + q * NTHR;
            if (q == 20) {
                float m = fmaxf(fmaxf(b[lane], b[lane + 32]),
                         fmaxf(fmaxf(b[lane + 64],  b[lane + 96]),
                         fmaxf(fmaxf(b[lane + 128], b[lane + 160]),
                               fmaxf(b[lane + 192], b[lane + 224]))));
                m = warp_max(m);
                if (lane == 0) res[q] = m;
            } else {
                float s = b[lane] + b[lane + 32] + b[lane + 64] + b[lane + 96]
                        + b[lane + 128] + b[lane + 160] + b[lane + 192] + b[lane + 224];
                s = warp_sum(s);
                if (lane == 0) res[q] = s;
            }
        }
        __syncthreads();

        if (tid == 0) {
            const float invfact[NMOM] = {1.0f, 1.0f, 0.5f, 1.0f/6.0f, 1.0f/24.0f, 1.0f/120.0f,
                                         1.0f/720.0f, 1.0f/5040.0f, 1.0f/40320.0f, 1.0f/362880.0f};
            g_envcoef[0]    = (float)KNOTS;
            g_envcoef[NMOM] = (float)KNOTS;
            #pragma unroll
            for (int n = 1; n < NMOM; n++) {
                g_envcoef[n]        = res[n - 1] * invfact[n];
                g_envcoef[NMOM + n] = res[8 + n] * invfact[n];
            }
            g_Rbase  = (float)(KNOTS - 1) * res[18];
            g_anyvar = (res[19] > 0.0f) ? 1 : 0;
            float phi0 = -lower;
            float phiE = fmaf((float)(S_PTS - 1) * INV_SAMP, lower + upper, -lower);
            float tmax = fmaxf(phi0 * phi0, phiE * phiE);
            float gate = res[20] * tmax;
            g_fastenv = (gate <= 1.0f) ? 1 : 0;   // NaN -> slow path
        }
        return;
    }

    // ---------------- mix blocks: 8 rows per block (one per warp) ------------
    __shared__ float sA[KNOTS], sB[KNOTS], sV0c[KNOTS], sSvj[KNOTS];
    __shared__ float sCb[KNOTS], sEm[KNOTS], sErl[KNOTS], sErh[KNOTS];
    __shared__ float sXs[KNOTS], sCw[KNOTS];
    __shared__ float red[32];
    __shared__ int s_nvar;

    if (tid == 0) s_nvar = 0;

    #pragma unroll
    for (int q = 0; q < 4; q++) {
        int k = tid + q * NTHR;
        float xk = x[k];
        float xlow  = (1.0f - lower) * xk;
        float xstep = ((upper - lower) * xk) * INV_SAMP;
        float rl = __expf(-klow[k]);
        float rh = __expf(-khigh[k]);
        float mean = kmean[k];
        float d  = xlow - mean;
        float r0 = (xlow <= mean) ? rl : rh;
        float a0 = d * r0;
        float v0 = __expf(-0.5f * a0 * a0);
        float B  = (float)S_PTS * v0;
        int cst = (xstep == 0.0f) ? 1 : 0;
        float v0c = cst ? v0 : 0.0f;
        float sp, cp;
        __sincosf(pol[k], &sp, &cp);

        sA[k]   = B;                 // fast-path A (overwritten on fallback)
        sB[k]   = B;
        sV0c[k] = v0c;
        sSvj[k] = sp * v0c;
        sCb[k]  = cp * B;
        sEm[k]  = emean[k];
        sErl[k] = __expf(-elow[k]);
        sErh[k] = __expf(-ehigh[k]);
        sXs[k]  = xstep;
        sCw[k]  = 0.0f;
        if (!cst) atomicAdd(&s_nvar, 1);
    }
    __syncthreads();

    // general fallback: recompute A; owning block materializes smear rows
    if (s_nvar > 0) {
        for (int k = 0; k < KNOTS; k++) {
            if (sXs[k] == 0.0f) continue;
            float xk = x[k];
            float xlow  = (1.0f - lower) * xk;
            float xstep = ((upper - lower) * xk) * INV_SAMP;
            float rl = __expf(-klow[k]);
            float rh = __expf(-khigh[k]);
            float mean = kmean[k];
            bool own = (bid == (k >> 3));   // 8 knots per owning block
            float* __restrict__ row = &g_smear[(size_t)k * S_PTS];
            float acc = 0.0f;
            for (int s = tid; s < S_PTS; s += NTHR) {
                float gv = fmaf(xstep, (float)s, xlow);
                float dd = gv - mean;
                float rr = (gv <= mean) ? rl : rh;
                float aa = dd * rr;
                float vv = __expf(-0.5f * aa * aa);
                if (own) row[s] = vv;
                acc += vv;
            }
            float tot = block_sum(acc, red);
            if (tid == 0) sA[k] = tot;
            __syncthreads();
        }
    }

    // mix: row i = bid*8 + warp; lane strides j (32 iterations)
    int warp = tid >> 5, lane = tid & 31;
    int i = bid * 8 + warp;
    float AiS  = sA[i] * (1.0f / (float)S_PTS);
    float Bi   = sB[i];
    float v0ci = sV0c[i];
    float rs = 0.0f, c1 = 0.0f, rp = 0.0f;
    #pragma unroll 8
    for (int j = lane; j < KNOTS; j += 32) {
        float corr = AiS * sA[j];
        float em = sEm[j];
        float dd = corr - em;
        float r  = (corr <= em) ? sErl[j] : sErh[j];
        float a  = dd * r;
        float e  = 0.5f * a * a;
        if (e < 88.0f) {                  // beyond this exp underflows to 0
            float m = __expf(-e);
            if (j == i) m = 0.0f;
            float cb = sCb[j];
            rs += m;
            c1 += m * cb;
            rp += m * (v0ci * (cb - 1.0f) + Bi * sSvj[j]);
            float v = Bi * m;
            if (v != 0.0f) atomicAdd(&sCw[j], v);
        }
    }
    rs = warp_sum(rs);
    c1 = warp_sum(c1);
    if (lane == 0) { g_rowsum[i] = rs; g_coef1[i] = c1; }

    float rpt = block_sum(rp, red);
    if (tid == 0) g_Rp[bid] = rpt;
    __syncthreads();

    // fallback cw partials (fully rewritten each run)
    #pragma unroll
    for (int q = 0; q < 4; q++) {
        int k = tid + q * NTHR;
        g_cwp[bid * KNOTS + k] = sCw[k];
    }
}

// ======================= K2: output (PDL-overlapped) ==========================
__global__ __launch_bounds__(NTHR, 1)
void k2_out(const float* __restrict__ x,
            const float* __restrict__ sw,
            const float* __restrict__ kmean,
            const float* __restrict__ klow,
            const float* __restrict__ khigh,
            const float* __restrict__ pol,
            float* __restrict__ out) {
    __shared__ float s_w[KNOTS], s_glow[KNOTS], s_gd[KNOTS];
    __shared__ float s_grl[KNOTS], s_grh[KNOTS], s_cst[KNOTS];

    const int tid = threadIdx.x;
    const int bid = blockIdx.x;
    const int lane = tid & 31;

    // -------- independent preamble (runs while k1 still executes) ------------
    const float lower = sw[0], upper = sw[1];
    int s = bid * NTHR + tid;
    float xi  = (float)s * INV_SAMP;
    float phi = fmaf(xi, lower + upper, -lower);
    float t   = phi * phi;

    // -------- wait for k1's results -------------------------------------------
#if defined(__CUDA_ARCH__) && (__CUDA_ARCH__ >= 900)
    cudaGridDependencySynchronize();
#endif

    const int anyvar  = g_anyvar;
    const int fastenv = g_fastenv;

    // R = Rbase + sum of 128 partials (lane-parallel, every warp redundantly)
    float rpart = g_Rp[lane] + g_Rp[lane + 32] + g_Rp[lane + 64] + g_Rp[lane + 96];
    float R = g_Rbase + warp_sum(rpart);

    // fallback: per-knot weights + envelope params (only if any nonconst knot)
    if (anyvar) {
        #pragma unroll
        for (int q = 0; q < 4; q++) {
            int k = tid + q * NTHR;
            float xk = x[k];
            float xlow  = (1.0f - lower) * xk;
            float xstep = ((upper - lower) * xk) * INV_SAMP;
            int cst = (xstep == 0.0f) ? 1 : 0;
            float cw = 0.0f;
            for (int p = 0; p < NMIX; p++) cw += g_cwp[p * KNOTS + k];
            float w = g_coef1[k] + (float)(KNOTS - 1) - g_rowsum[k]
                    + __sinf(pol[k]) * cw;
            s_w[k]   = w;
            s_cst[k] = (float)cst;
            float highs = (1.0f + upper) * xk;
            s_glow[k] = xlow;  s_gd[k] = highs - xlow;
            s_grl[k]  = __expf(-xlow);
            s_grh[k]  = __expf(-highs);
        }
        __syncthreads();
    }

    if (s >= S_PTS) return;

    float env;
    if (fastenv) {
        const float* cf = g_envcoef + ((phi <= 0.0f) ? 0 : NMOM);
        float u = -t;
        env = cf[NMOM - 1];
        #pragma unroll
        for (int n = NMOM - 2; n >= 0; n--) env = fmaf(env, u, cf[n]);
    } else {
        env = 0.0f;
        for (int k = 0; k < KNOTS; k++) {
            float mean = x[k];
            float gv = fmaf(s_gd[k], xi, s_glow[k]);
            float dd = gv - mean;
            float r  = (gv <= mean) ? s_grl[k] : s_grh[k];
            float a  = dd * r;
            env += __expf(-0.5f * a * a);
        }
    }

    float res = R;
    if (anyvar) {
        for (int k = 0; k < KNOTS; k++) {
            if (s_cst[k] == 0.0f)
                res = fmaf(s_w[k], g_smear[(size_t)k * S_PTS + s], res);
        }
    }
    out[s] = env * res;
}

// ---------------- launch ------------------------------------------------------
extern "C" void kernel_launch(void* const* d_in, const int* in_sizes, int n_in,
                              void* d_out, int out_size) {
    const float* x     = (const float*)d_in[0];
    const float* sw    = (const float*)d_in[1];
    const float* kmean = (const float*)d_in[2];
    const float* klow  = (const float*)d_in[3];
    const float* khigh = (const float*)d_in[4];
    const float* emean = (const float*)d_in[5];
    const float* elow  = (const float*)d_in[6];
    const float* ehigh = (const float*)d_in[7];
    const float* pol   = (const float*)d_in[8];
    float* out = (float*)d_out;

    k1_mix<<<NBLK1, NTHR>>>(x, sw, kmean, klow, khigh, emean, elow, ehigh, pol);

    // k2 with programmatic dependent launch: pre-launch under k1, sync inside.
    cudaLaunchConfig_t cfg = {};
    cfg.gridDim  = dim3(NBLK2, 1, 1);
    cfg.blockDim = dim3(NTHR, 1, 1);
    cfg.dynamicSmemBytes = 0;
    cfg.stream = 0;
    cudaLaunchAttribute attr[1];
    attr[0].id = cudaLaunchAttributeProgrammaticStreamSerialization;
    attr[0].val.programmaticStreamSerializationAllowed = 1;
    cfg.attrs = attr;
    cfg.numAttrs = 1;
    cudaError_t e = cudaLaunchKernelEx(&cfg, k2_out, x, sw, kmean, klow, khigh, pol, out);
    if (e != cudaSuccess) {
        // PDL unsupported in this capture context: plain launch (still correct)
        k2_out<<<NBLK2, NTHR>>>(x, sw, kmean, klow, khigh, pol, out);
    }
}

// round 7
// speedup vs baseline: 4.2567x; 1.2835x over previous
#include <cuda_runtime.h>
#include <math.h>

#define KNOTS   1024
#define S_PTS   4095
#define INV_SAMP (1.0f / 4096.0f)
#define NMOM  10
#define NBLK  16
#define NTHR  256
#define TGUARD 13.3f          // conservative: e<88 <=> |a|<13.2665

// ---------------- scratch (device globals; slow path only) -------------------
__device__ float g_smear[(size_t)KNOTS * S_PTS];
__device__ float g_rowsum[KNOTS], g_coef1[KNOTS];
__device__ float g_cwp[NBLK * KNOTS];
__device__ float g_Rp[NBLK];
__device__ unsigned g_count = 0;   // self-resetting per barrier episode
__device__ unsigned g_gen   = 0;   // monotone across graph replays

// ---------------- reductions --------------------------------------------------
__device__ __forceinline__ float warp_sum(float v) {
    #pragma unroll
    for (int o = 16; o > 0; o >>= 1) v += __shfl_xor_sync(0xFFFFFFFFu, v, o);
    return v;
}
__device__ __forceinline__ float warp_max(float v) {
    #pragma unroll
    for (int o = 16; o > 0; o >>= 1) v = fmaxf(v, __shfl_xor_sync(0xFFFFFFFFu, v, o));
    return v;
}
__device__ __forceinline__ float warp_min(float v) {
    #pragma unroll
    for (int o = 16; o > 0; o >>= 1) v = fminf(v, __shfl_xor_sync(0xFFFFFFFFu, v, o));
    return v;
}
// broadcast block reductions (result valid in ALL threads)
__device__ __forceinline__ float block_sum_b(float v, float* red) {
    int tid = threadIdx.x;
    v = warp_sum(v);
    if ((tid & 31) == 0) red[tid >> 5] = v;
    __syncthreads();
    if (tid == 0) {
        float r = red[0];
        #pragma unroll
        for (int w = 1; w < NTHR / 32; w++) r += red[w];
        red[16] = r;
    }
    __syncthreads();
    float out = red[16];
    __syncthreads();
    return out;
}
__device__ __forceinline__ float block_min_b(float v, float* red) {
    int tid = threadIdx.x;
    v = warp_min(v);
    if ((tid & 31) == 0) red[tid >> 5] = v;
    __syncthreads();
    if (tid == 0) {
        float r = red[0];
        #pragma unroll
        for (int w = 1; w < NTHR / 32; w++) r = fminf(r, red[w]);
        red[16] = r;
    }
    __syncthreads();
    float out = red[16];
    __syncthreads();
    return out;
}
__device__ __forceinline__ float block_max_b(float v, float* red) {
    int tid = threadIdx.x;
    v = warp_max(v);
    if ((tid & 31) == 0) red[tid >> 5] = v;
    __syncthreads();
    if (tid == 0) {
        float r = red[0];
        #pragma unroll
        for (int w = 1; w < NTHR / 32; w++) r = fmaxf(r, red[w]);
        red[16] = r;
    }
    __syncthreads();
    float out = red[16];
    __syncthreads();
    return out;
}

// ---------------- software grid barrier (slow path only) ---------------------
__device__ __forceinline__ void grid_barrier() {
    __threadfence();
    __syncthreads();
    if (threadIdx.x == 0) {
        unsigned my = *((volatile unsigned*)&g_gen);
        if (atomicAdd(&g_count, 1u) == NBLK - 1) {
            g_count = 0;
            __threadfence();
            *((volatile unsigned*)&g_gen) = my + 1;
        } else {
            while (*((volatile unsigned*)&g_gen) == my) { }
        }
        __threadfence();
    }
    __syncthreads();
}

// ======================= the single kernel ====================================
__global__ __launch_bounds__(NTHR, 1)
void knot_one(const float* __restrict__ x,
              const float* __restrict__ sw,
              const float* __restrict__ kmean,
              const float* __restrict__ klow,
              const float* __restrict__ khigh,
              const float* __restrict__ emean,
              const float* __restrict__ elow,
              const float* __restrict__ ehigh,
              const float* __restrict__ pol,
              float* __restrict__ out) {
    // 37 KB pool, aliased per phase:
    //   stats:   buf[21*256]                    (21504 B)
    //   slowmix: sA,sB,sV0c,sSvj,sCb,sEm,sErl,sErh,sCw (9*4096 B)
    //   output:  s_w, s_glow, s_gd, s_grl, s_grh, s_cst (6*4096 B)
    __shared__ float pool[9472];
    __shared__ float red[17];
    __shared__ float s_res[21];
    __shared__ float s_cf[2 * NMOM];
    __shared__ int   s_fastenv;

    const int tid = threadIdx.x;
    const int bid = blockIdx.x;
    const float lower = sw[0], upper = sw[1];

    // =============== per-thread knot quantities (4 knots/thread) =============
    float B4[4], v0c4[4], clo4[4], chi4[4];
    float nv = 0.0f;
    #pragma unroll
    for (int q = 0; q < 4; q++) {
        int k = tid + q * NTHR;
        float xk = x[k];
        float xlow  = (1.0f - lower) * xk;
        float xstep = ((upper - lower) * xk) * INV_SAMP;
        int cst = (xstep == 0.0f) ? 1 : 0;
        float rl = __expf(-klow[k]);
        float rh = __expf(-khigh[k]);
        float mean = kmean[k];
        float d  = xlow - mean;
        float r0 = (xlow <= mean) ? rl : rh;
        float a0 = d * r0;
        float v0 = __expf(-0.5f * a0 * a0);
        float B  = (float)S_PTS * v0;
        B4[q]   = B;
        v0c4[q] = cst ? v0 : 0.0f;
        if (!cst) nv += 1.0f;

        float highs = (1.0f + upper) * xk;
        float erlw = __expf(-xlow);
        float erhg = __expf(-highs);
        float hlo = xk * erlw, hhi = xk * erhg;
        clo4[q] = 0.5f * hlo * hlo;
        chi4[q] = 0.5f * hhi * hhi;
    }

    // round 1: Amin / Amax / anyvar  (broadcast)
    float bmin = fminf(fminf(B4[0], B4[1]), fminf(B4[2], B4[3]));
    float bmax = fmaxf(fmaxf(B4[0], B4[1]), fmaxf(B4[2], B4[3]));
    float Amin = block_min_b(bmin, red);
    float Amax = block_max_b(bmax, red);
    float NV   = block_sum_b(nv, red);

    // mix-pass-possible flags (per j), using corr range [Amin,Amax]*B_j/S
    float anyp = 0.0f;
    #pragma unroll
    for (int q = 0; q < 4; q++) {
        int k = tid + q * NTHR;
        float em  = emean[k];
        float rle = __expf(-elow[k]);
        float rhe = __expf(-ehigh[k]);
        float lo = em - TGUARD / rle;
        float hi = em + TGUARD / rhe;
        float cminj = Amin * B4[q] * (1.0f / (float)S_PTS);
        float cmaxj = Amax * B4[q] * (1.0f / (float)S_PTS);
        // NaN-safe: NaN comparisons false -> pass=1 -> slow path
        float pass = (!(cmaxj < lo) && !(cminj > hi)) ? 1.0f : 0.0f;
        anyp += pass;
    }

    // =============== round 2: batched 21-quantity reduction ==================
    {
        float* buf = pool;
        float plp[4] = {1,1,1,1}, php[4] = {1,1,1,1};
        #pragma unroll
        for (int n = 1; n < NMOM; n++) {
            float sl = 0.0f, sh2 = 0.0f;
            #pragma unroll
            for (int q = 0; q < 4; q++) {
                plp[q] *= clo4[q]; php[q] *= chi4[q];
                sl += plp[q]; sh2 += php[q];
            }
            buf[(n - 1) * NTHR + tid] = sl;     // q 0..8 : low moments
            buf[(8 + n) * NTHR + tid] = sh2;    // q 9..17: high moments
        }
        buf[18 * NTHR + tid] = v0c4[0] + v0c4[1] + v0c4[2] + v0c4[3];  // v0 sum (const)
        buf[19 * NTHR + tid] = anyp;                                    // pass count
        buf[20 * NTHR + tid] = fmaxf(fmaxf(clo4[0], chi4[0]),
                               fmaxf(fmaxf(clo4[1], chi4[1]),
                               fmaxf(fmaxf(clo4[2], chi4[2]),
                                     fmaxf(clo4[3], chi4[3]))));        // max c
        __syncthreads();

        int warp = tid >> 5, lane = tid & 31;
        for (int q = warp; q < 21; q += 8) {
            const float* b = buf + q * NTHR;
            if (q == 20) {
                float m = fmaxf(fmaxf(b[lane], b[lane + 32]),
                         fmaxf(fmaxf(b[lane + 64],  b[lane + 96]),
                         fmaxf(fmaxf(b[lane + 128], b[lane + 160]),
                               fmaxf(b[lane + 192], b[lane + 224]))));
                m = warp_max(m);
                if (lane == 0) s_res[q] = m;
            } else {
                float s = b[lane] + b[lane + 32] + b[lane + 64] + b[lane + 96]
                        + b[lane + 128] + b[lane + 160] + b[lane + 192] + b[lane + 224];
                s = warp_sum(s);
                if (lane == 0) s_res[q] = s;
            }
        }
        __syncthreads();
    }

    const int slow = (NV > 0.0f) || (s_res[19] > 0.0f);
    float R = (float)(KNOTS - 1) * s_res[18];    // Rbase

    // envelope Taylor coefficients + gate
    if (tid == 0) {
        const float invfact[NMOM] = {1.0f, 1.0f, 0.5f, 1.0f/6.0f, 1.0f/24.0f, 1.0f/120.0f,
                                     1.0f/720.0f, 1.0f/5040.0f, 1.0f/40320.0f, 1.0f/362880.0f};
        s_cf[0]    = (float)KNOTS;
        s_cf[NMOM] = (float)KNOTS;
        #pragma unroll
        for (int n = 1; n < NMOM; n++) {
            s_cf[n]        = s_res[n - 1] * invfact[n];
            s_cf[NMOM + n] = s_res[8 + n] * invfact[n];
        }
        float phi0 = -lower;
        float phiE = fmaf((float)(S_PTS - 1) * INV_SAMP, lower + upper, -lower);
        float tmax = fmaxf(phi0 * phi0, phiE * phiE);
        float gate = s_res[20] * tmax;
        s_fastenv = (gate <= 1.0f) ? 1 : 0;      // NaN -> slow env loop
    }
    __syncthreads();

    // ======================= SLOW PATH (general correctness) =================
    float* s_w    = pool;
    float* s_glow = pool + 1024;
    float* s_gd   = pool + 2048;
    float* s_grl  = pool + 3072;
    float* s_grh  = pool + 4096;
    float* s_cst  = pool + 5120;

    if (slow) {
        // mix arrays (alias pool)
        float* sA   = pool;
        float* sB   = pool + 1024;
        float* sV0c = pool + 2048;
        float* sSvj = pool + 3072;
        float* sCb  = pool + 4096;
        float* sEm  = pool + 5120;
        float* sErl = pool + 6144;
        float* sErh = pool + 7168;
        float* sCw  = pool + 8192;

        #pragma unroll
        for (int q = 0; q < 4; q++) {
            int k = tid + q * NTHR;
            float sp, cp;
            __sincosf(pol[k], &sp, &cp);
            sA[k]   = B4[q];
            sB[k]   = B4[q];
            sV0c[k] = v0c4[q];
            sSvj[k] = sp * v0c4[q];
            sCb[k]  = cp * B4[q];
            sEm[k]  = emean[k];
            sErl[k] = __expf(-elow[k]);
            sErh[k] = __expf(-ehigh[k]);
            sCw[k]  = 0.0f;
        }
        __syncthreads();

        // non-constant knots: true A via S-loop; owning block stores smear rows
        if (NV > 0.0f) {
            for (int k = 0; k < KNOTS; k++) {
                float xk = x[k];
                float xstep = ((upper - lower) * xk) * INV_SAMP;
                if (xstep == 0.0f) continue;
                float xlow = (1.0f - lower) * xk;
                float rl = __expf(-klow[k]);
                float rh = __expf(-khigh[k]);
                float mean = kmean[k];
                bool own = (bid == (k >> 6));    // 64 knots per owning block
                float* __restrict__ row = &g_smear[(size_t)k * S_PTS];
                float acc = 0.0f;
                for (int s = tid; s < S_PTS; s += NTHR) {
                    float gv = fmaf(xstep, (float)s, xlow);
                    float dd = gv - mean;
                    float rr = (gv <= mean) ? rl : rh;
                    float aa = dd * rr;
                    float vv = __expf(-0.5f * aa * aa);
                    if (own) row[s] = vv;
                    acc += vv;
                }
                float tot = block_sum_b(acc, red);
                if (tid == 0) sA[k] = tot;
                __syncthreads();
            }
        }

        // mix: 64 rows/block = 8 warps x 8 rows
        int warp = tid >> 5, lane = tid & 31;
        float rp = 0.0f;
        #pragma unroll
        for (int rr = 0; rr < 8; rr++) {
            int i = bid * 64 + rr * 8 + warp;
            float AiS  = sA[i] * (1.0f / (float)S_PTS);
            float Bi   = sB[i];
            float v0ci = sV0c[i];
            float rs = 0.0f, c1 = 0.0f;
            for (int j = lane; j < KNOTS; j += 32) {
                float corr = AiS * sA[j];
                float em = sEm[j];
                float dd = corr - em;
                float r  = (corr <= em) ? sErl[j] : sErh[j];
                float a  = dd * r;
                float e  = 0.5f * a * a;
                if (e < 88.0f) {
                    float m = __expf(-e);
                    if (j == i) m = 0.0f;
                    float cb = sCb[j];
                    rs += m;
                    c1 += m * cb;
                    rp += m * (v0ci * (cb - 1.0f) + Bi * sSvj[j]);
                    float v = Bi * m;
                    if (v != 0.0f) atomicAdd(&sCw[j], v);
                }
            }
            rs = warp_sum(rs);
            c1 = warp_sum(c1);
            if (lane == 0) { g_rowsum[i] = rs; g_coef1[i] = c1; }
        }
        float rpt = block_sum_b(rp, red);
        if (tid == 0) g_Rp[bid] = rpt;
        __syncthreads();
        #pragma unroll
        for (int q = 0; q < 4; q++) {
            int k = tid + q * NTHR;
            g_cwp[bid * KNOTS + k] = sCw[k];
        }

        grid_barrier();

        // R = Rbase + sum of 16 partials
        #pragma unroll
        for (int p = 0; p < NBLK; p++) R += g_Rp[p];

        // weights + env params (mix arrays dead; reuse pool for output arrays)
        __syncthreads();
        #pragma unroll
        for (int q = 0; q < 4; q++) {
            int k = tid + q * NTHR;
            float xk = x[k];
            float xlow  = (1.0f - lower) * xk;
            float xstep = ((upper - lower) * xk) * INV_SAMP;
            float cw = 0.0f;
            #pragma unroll
            for (int p = 0; p < NBLK; p++) cw += g_cwp[p * KNOTS + k];
            float w = g_coef1[k] + (float)(KNOTS - 1) - g_rowsum[k]
                    + __sinf(pol[k]) * cw;
            float highs = (1.0f + upper) * xk;
            s_w[k]    = w;
            s_cst[k]  = (xstep == 0.0f) ? 1.0f : 0.0f;
            s_glow[k] = xlow;
            s_gd[k]   = highs - xlow;
            s_grl[k]  = __expf(-xlow);
            s_grh[k]  = __expf(-highs);
        }
        __syncthreads();
    } else if (!s_fastenv) {
        // fast path but envelope needs the exact per-knot loop
        __syncthreads();   // buf dead
        #pragma unroll
        for (int q = 0; q < 4; q++) {
            int k = tid + q * NTHR;
            float xk = x[k];
            float xlow  = (1.0f - lower) * xk;
            float highs = (1.0f + upper) * xk;
            s_glow[k] = xlow;
            s_gd[k]   = highs - xlow;
            s_grl[k]  = __expf(-xlow);
            s_grh[k]  = __expf(-highs);
        }
        __syncthreads();
    }

    // ======================= output ===========================================
    int s = bid * NTHR + tid;
    if (s >= S_PTS) return;

    float xi  = (float)s * INV_SAMP;
    float phi = fmaf(xi, lower + upper, -lower);
    float t   = phi * phi;

    float env;
    if (s_fastenv) {
        const float* cf = s_cf + ((phi <= 0.0f) ? 0 : NMOM);
        float u = -t;
        env = cf[NMOM - 1];
        #pragma unroll
        for (int n = NMOM - 2; n >= 0; n--) env = fmaf(env, u, cf[n]);
    } else {
        env = 0.0f;
        for (int k = 0; k < KNOTS; k++) {
            float mean = x[k];
            float gv = fmaf(s_gd[k], xi, s_glow[k]);
            float dd = gv - mean;
            float r  = (gv <= mean) ? s_grl[k] : s_grh[k];
            float a  = dd * r;
            env += __expf(-0.5f * a * a);
        }
    }

    float res = R;
    if (slow && NV > 0.0f) {
        for (int k = 0; k < KNOTS; k++) {
            if (s_cst[k] == 0.0f)
                res = fmaf(s_w[k], g_smear[(size_t)k * S_PTS + s], res);
        }
    }
    out[s] = env * res;
}

// ---------------- launch ------------------------------------------------------
extern "C" void kernel_launch(void* const* d_in, const int* in_sizes, int n_in,
                              void* d_out, int out_size) {
    const float* x     = (const float*)d_in[0];
    const float* sw    = (const float*)d_in[1];
    const float* kmean = (const float*)d_in[2];
    const float* klow  = (const float*)d_in[3];
    const float* khigh = (const float*)d_in[4];
    const float* emean = (const float*)d_in[5];
    const float* elow  = (const float*)d_in[6];
    const float* ehigh = (const float*)d_in[7];
    const float* pol   = (const float*)d_in[8];
    float* out = (float*)d_out;

    knot_one<<<NBLK, NTHR>>>(x, sw, kmean, klow, khigh, emean, elow, ehigh, pol, out);
}

// round 8
// speedup vs baseline: 5.3413x; 1.2548x over previous
#include <cuda_runtime.h>
#include <math.h>

#define KNOTS   1024
#define S_PTS   4095
#define INV_SAMP (1.0f / 4096.0f)
#define INV_S    (1.0f / (float)S_PTS)
#define NMOM   7            // Taylor n = 0..6 (gate 0.1 -> err <= 2e-11/knot)
#define GATE   0.1f
#define NBLK   8
#define NTHR   512
#define TGUARD 13.3f        // conservative: e<88 <=> |a|<13.2665

// ---------------- scratch (device globals; slow path only) -------------------
__device__ float g_smear[(size_t)KNOTS * S_PTS];
__device__ float g_rowsum[KNOTS], g_coef1[KNOTS];
__device__ float g_cwp[NBLK * KNOTS];
__device__ float g_Rp[NBLK];
__device__ unsigned g_count = 0;   // self-resetting per barrier episode
__device__ unsigned g_gen   = 0;   // monotone across graph replays

// ---------------- warp helpers -------------------------------------------------
__device__ __forceinline__ float warp_sum(float v) {
    #pragma unroll
    for (int o = 16; o > 0; o >>= 1) v += __shfl_xor_sync(0xFFFFFFFFu, v, o);
    return v;
}
__device__ __forceinline__ float warp_max(float v) {
    #pragma unroll
    for (int o = 16; o > 0; o >>= 1) v = fmaxf(v, __shfl_xor_sync(0xFFFFFFFFu, v, o));
    return v;
}
__device__ __forceinline__ float warp_min(float v) {
    #pragma unroll
    for (int o = 16; o > 0; o >>= 1) v = fminf(v, __shfl_xor_sync(0xFFFFFFFFu, v, o));
    return v;
}
// broadcast block sum for the slow path (512 threads = 16 warps)
__device__ __forceinline__ float block_sum_b(float v, float* red) {
    int tid = threadIdx.x;
    v = warp_sum(v);
    if ((tid & 31) == 0) red[tid >> 5] = v;
    __syncthreads();
    if (tid == 0) {
        float r = red[0];
        #pragma unroll
        for (int w = 1; w < NTHR / 32; w++) r += red[w];
        red[16] = r;
    }
    __syncthreads();
    float o = red[16];
    __syncthreads();
    return o;
}

// ---------------- software grid barrier (slow path only) ---------------------
__device__ __forceinline__ void grid_barrier() {
    __threadfence();
    __syncthreads();
    if (threadIdx.x == 0) {
        unsigned my = *((volatile unsigned*)&g_gen);
        if (atomicAdd(&g_count, 1u) == NBLK - 1) {
            g_count = 0;
            __threadfence();
            *((volatile unsigned*)&g_gen) = my + 1;
        } else {
            while (*((volatile unsigned*)&g_gen) == my) { }
        }
        __threadfence();
    }
    __syncthreads();
}

// ======================= the single kernel ====================================
__global__ __launch_bounds__(NTHR, 1)
void knot_one(const float* __restrict__ x,
              const float* __restrict__ sw,
              const float* __restrict__ kmean,
              const float* __restrict__ klow,
              const float* __restrict__ khigh,
              const float* __restrict__ emean,
              const float* __restrict__ elow,
              const float* __restrict__ ehigh,
              const float* __restrict__ pol,
              float* __restrict__ out) {
    // pool (36 KB) aliased per phase:
    //   fast reduce:  buf[16 * 512]                      (32 KB)
    //   slow mix:     9 arrays x 1024                    (36 KB)
    //   slow output:  6 arrays x 1024                    (24 KB)
    __shared__ float pool[9216];
    __shared__ float red[17];
    __shared__ float s_res[16];
    __shared__ float s_cf[2 * NMOM];
    __shared__ int   s_fastenv;

    const int tid  = threadIdx.x;
    const int bid  = blockIdx.x;
    const int warp = tid >> 5, lane = tid & 31;
    const float lower = sw[0], upper = sw[1];

    // =============== phase 1: per-thread knot quantities (2 knots) ===========
    float B2[2], v0c2[2], clo2[2], chi2[2], em2[2], eel2[2], eeh2[2];
    int noncst = 0;
    #pragma unroll
    for (int q = 0; q < 2; q++) {
        int k = tid + q * NTHR;
        float xk    = x[k];
        float kml   = klow[k];
        float kmh   = khigh[k];
        float mean  = kmean[k];
        float el    = elow[k];
        float eh    = ehigh[k];
        float xlow  = (1.0f - lower) * xk;
        float xstep = ((upper - lower) * xk) * INV_SAMP;
        int   cst   = (xstep == 0.0f) ? 1 : 0;
        float rl = __expf(-kml);
        float rh = __expf(-kmh);
        float d  = xlow - mean;
        float r0 = (xlow <= mean) ? rl : rh;
        float a0 = d * r0;
        float v0 = __expf(-0.5f * a0 * a0);
        float B  = (float)S_PTS * v0;
        B2[q]   = B;
        v0c2[q] = cst ? v0 : 0.0f;
        if (!cst) noncst = 1;

        float highs = (1.0f + upper) * xk;
        float erlw = __expf(-xlow);
        float erhg = __expf(-highs);
        float hlo = xk * erlw, hhi = xk * erhg;
        clo2[q] = 0.5f * hlo * hlo;
        chi2[q] = 0.5f * hhi * hhi;

        em2[q]  = emean[k];
        eel2[q] = __expf(el);    // TGUARD/exp(-elow) == TGUARD*exp(elow)
        eeh2[q] = __expf(eh);
    }

    // =============== phase 2: single batched 16-quantity reduction ===========
    {
        float* buf = pool;
        float pl0 = clo2[0], pl1 = clo2[1], ph0 = chi2[0], ph1 = chi2[1];
        #pragma unroll
        for (int n = 1; n <= 6; n++) {
            buf[(n - 1) * NTHR + tid] = pl0 + pl1;       // q 0..5 : low moments
            buf[(5 + n) * NTHR + tid] = ph0 + ph1;       // q 6..11: high moments
            pl0 *= clo2[0]; pl1 *= clo2[1];
            ph0 *= chi2[0]; ph1 *= chi2[1];
        }
        buf[12 * NTHR + tid] = v0c2[0] + v0c2[1];                          // v0 sum
        buf[13 * NTHR + tid] = fmaxf(fmaxf(clo2[0], chi2[0]),
                                     fmaxf(clo2[1], chi2[1]));             // cmax
        buf[14 * NTHR + tid] = fminf(B2[0], B2[1]);                        // Bmin
        buf[15 * NTHR + tid] = fmaxf(B2[0], B2[1]);                        // Bmax
    }
    int anyvar = __syncthreads_or(noncst);   // doubles as the buf barrier

    {
        const float* b = pool + warp * NTHR;
        float a0 = b[lane], a1 = b[lane + 32], a2 = b[lane + 64], a3 = b[lane + 96];
        float a4 = b[lane + 128], a5 = b[lane + 160], a6 = b[lane + 192], a7 = b[lane + 224];
        float a8 = b[lane + 256], a9 = b[lane + 288], aA = b[lane + 320], aB = b[lane + 352];
        float aC = b[lane + 384], aD = b[lane + 416], aE = b[lane + 448], aF = b[lane + 480];
        float v;
        if (warp == 13 || warp == 15) {       // max
            v = fmaxf(fmaxf(fmaxf(a0, a1), fmaxf(a2, a3)),
                      fmaxf(fmaxf(a4, a5), fmaxf(a6, a7)));
            v = fmaxf(v, fmaxf(fmaxf(fmaxf(a8, a9), fmaxf(aA, aB)),
                               fmaxf(fmaxf(aC, aD), fmaxf(aE, aF))));
            v = warp_max(v);
        } else if (warp == 14) {              // min
            v = fminf(fminf(fminf(a0, a1), fminf(a2, a3)),
                      fminf(fminf(a4, a5), fminf(a6, a7)));
            v = fminf(v, fminf(fminf(fminf(a8, a9), fminf(aA, aB)),
                               fminf(fminf(aC, aD), fminf(aE, aF))));
            v = warp_min(v);
        } else {                              // sum
            v = ((a0 + a1) + (a2 + a3)) + ((a4 + a5) + (a6 + a7))
              + ((a8 + a9) + (aA + aB)) + ((aC + aD) + (aE + aF));
            v = warp_sum(v);
        }
        if (lane == 0) s_res[warp] = v;
    }
    __syncthreads();

    // =============== phase 3: mix-pass test + coefficients ===================
    const float Bmin = s_res[14], Bmax = s_res[15];
    int pass = 0;
    #pragma unroll
    for (int q = 0; q < 2; q++) {
        float lo = em2[q] - TGUARD * eel2[q];
        float hi = em2[q] + TGUARD * eeh2[q];
        float cminj = Bmin * B2[q] * INV_S;
        float cmaxj = Bmax * B2[q] * INV_S;
        // NaN-safe: NaN comparisons are false -> pass=1 -> slow path
        if (!(cmaxj < lo) && !(cminj > hi)) pass = 1;
    }
    const int slow = __syncthreads_or(pass) | anyvar;

    if (tid < 2 * NMOM) {
        const float invfact[NMOM] = {1.0f, 1.0f, 0.5f, 1.0f/6.0f, 1.0f/24.0f,
                                     1.0f/120.0f, 1.0f/720.0f};
        int side = (tid >= NMOM) ? 1 : 0;
        int n    = tid - side * NMOM;
        s_cf[tid] = (n == 0) ? (float)KNOTS
                             : s_res[side * 6 + (n - 1)] * invfact[n];
        if (tid == 0) {
            float phi0 = -lower;
            float phiE = fmaf((float)(S_PTS - 1) * INV_SAMP, lower + upper, -lower);
            float tmax = fmaxf(phi0 * phi0, phiE * phiE);
            float gate = s_res[13] * tmax;
            s_fastenv = (gate <= GATE) ? 1 : 0;   // NaN -> slow env loop
        }
    }
    float R = (float)(KNOTS - 1) * s_res[12];      // Rbase
    __syncthreads();

    // ======================= SLOW PATH (general correctness) =================
    float* s_w    = pool;
    float* s_glow = pool + 1024;
    float* s_gd   = pool + 2048;
    float* s_grl  = pool + 3072;
    float* s_grh  = pool + 4096;
    float* s_cst  = pool + 5120;

    if (slow) {
        float* sA   = pool;
        float* sB   = pool + 1024;
        float* sV0c = pool + 2048;
        float* sSvj = pool + 3072;
        float* sCb  = pool + 4096;
        float* sEm  = pool + 5120;
        float* sErl = pool + 6144;
        float* sErh = pool + 7168;
        float* sCw  = pool + 8192;

        #pragma unroll
        for (int q = 0; q < 2; q++) {
            int k = tid + q * NTHR;
            float sp, cp;
            __sincosf(pol[k], &sp, &cp);
            sA[k]   = B2[q];
            sB[k]   = B2[q];
            sV0c[k] = v0c2[q];
            sSvj[k] = sp * v0c2[q];
            sCb[k]  = cp * B2[q];
            sEm[k]  = em2[q];
            sErl[k] = 1.0f / eel2[q];   // exp(-elow)
            sErh[k] = 1.0f / eeh2[q];   // exp(-ehigh)
            sCw[k]  = 0.0f;
        }
        __syncthreads();

        // non-constant knots: true A via S-loop; owning block stores smear rows
        if (anyvar) {
            for (int k = 0; k < KNOTS; k++) {
                float xk = x[k];
                float xstep = ((upper - lower) * xk) * INV_SAMP;
                if (xstep == 0.0f) continue;
                float xlow = (1.0f - lower) * xk;
                float rl = __expf(-klow[k]);
                float rh = __expf(-khigh[k]);
                float mean = kmean[k];
                bool own = (bid == (k >> 7));    // 128 knots per owning block
                float* __restrict__ row = &g_smear[(size_t)k * S_PTS];
                float acc = 0.0f;
                for (int s = tid; s < S_PTS; s += NTHR) {
                    float gv = fmaf(xstep, (float)s, xlow);
                    float dd = gv - mean;
                    float rr = (gv <= mean) ? rl : rh;
                    float aa = dd * rr;
                    float vv = __expf(-0.5f * aa * aa);
                    if (own) row[s] = vv;
                    acc += vv;
                }
                float tot = block_sum_b(acc, red);
                if (tid == 0) sA[k] = tot;
                __syncthreads();
            }
        }

        // mix: 128 rows/block = 16 warps x 8 rows
        float rp = 0.0f;
        #pragma unroll
        for (int rr = 0; rr < 8; rr++) {
            int i = bid * 128 + rr * 16 + warp;
            float AiS  = sA[i] * INV_S;
            float Bi   = sB[i];
            float v0ci = sV0c[i];
            float rs = 0.0f, c1 = 0.0f;
            for (int j = lane; j < KNOTS; j += 32) {
                float corr = AiS * sA[j];
                float em = sEm[j];
                float dd = corr - em;
                float r  = (corr <= em) ? sErl[j] : sErh[j];
                float a  = dd * r;
                float e  = 0.5f * a * a;
                if (e < 88.0f) {
                    float m = __expf(-e);
                    if (j == i) m = 0.0f;
                    float cb = sCb[j];
                    rs += m;
                    c1 += m * cb;
                    rp += m * (v0ci * (cb - 1.0f) + Bi * sSvj[j]);
                    float v = Bi * m;
                    if (v != 0.0f) atomicAdd(&sCw[j], v);
                }
            }
            rs = warp_sum(rs);
            c1 = warp_sum(c1);
            if (lane == 0) { g_rowsum[i] = rs; g_coef1[i] = c1; }
        }
        float rpt = block_sum_b(rp, red);
        if (tid == 0) g_Rp[bid] = rpt;
        __syncthreads();
        #pragma unroll
        for (int q = 0; q < 2; q++) {
            int k = tid + q * NTHR;
            g_cwp[bid * KNOTS + k] = sCw[k];
        }

        grid_barrier();

        #pragma unroll
        for (int p = 0; p < NBLK; p++) R += g_Rp[p];

        __syncthreads();
        #pragma unroll
        for (int q = 0; q < 2; q++) {
            int k = tid + q * NTHR;
            float xk = x[k];
            float xlow  = (1.0f - lower) * xk;
            float xstep = ((upper - lower) * xk) * INV_SAMP;
            float cw = 0.0f;
            #pragma unroll
            for (int p = 0; p < NBLK; p++) cw += g_cwp[p * KNOTS + k];
            float w = g_coef1[k] + (float)(KNOTS - 1) - g_rowsum[k]
                    + __sinf(pol[k]) * cw;
            float highs = (1.0f + upper) * xk;
            s_w[k]    = w;
            s_cst[k]  = (xstep == 0.0f) ? 1.0f : 0.0f;
            s_glow[k] = xlow;
            s_gd[k]   = highs - xlow;
            s_grl[k]  = __expf(-xlow);
            s_grh[k]  = __expf(-highs);
        }
        __syncthreads();
    } else if (!s_fastenv) {
        // fast path but envelope needs the exact per-knot loop
        __syncthreads();   // buf dead
        #pragma unroll
        for (int q = 0; q < 2; q++) {
            int k = tid + q * NTHR;
            float xk = x[k];
            float xlow  = (1.0f - lower) * xk;
            float highs = (1.0f + upper) * xk;
            s_glow[k] = xlow;
            s_gd[k]   = highs - xlow;
            s_grl[k]  = __expf(-xlow);
            s_grh[k]  = __expf(-highs);
        }
        __syncthreads();
    }

    // ======================= output (1 sample / thread) ======================
    int s = bid * NTHR + tid;
    if (s >= S_PTS) return;

    float xi  = (float)s * INV_SAMP;
    float phi = fmaf(xi, lower + upper, -lower);
    float t   = phi * phi;

    float env;
    if (s_fastenv) {
        const float* cf = s_cf + ((phi <= 0.0f) ? 0 : NMOM);
        float u = -t;
        env = cf[NMOM - 1];
        #pragma unroll
        for (int n = NMOM - 2; n >= 0; n--) env = fmaf(env, u, cf[n]);
    } else {
        env = 0.0f;
        for (int k = 0; k < KNOTS; k++) {
            float mean = x[k];
            float gv = fmaf(s_gd[k], xi, s_glow[k]);
            float dd = gv - mean;
            float r  = (gv <= mean) ? s_grl[k] : s_grh[k];
            float a  = dd * r;
            env += __expf(-0.5f * a * a);
        }
    }

    float res = R;
    if (slow && anyvar) {
        for (int k = 0; k < KNOTS; k++) {
            if (s_cst[k] == 0.0f)
                res = fmaf(s_w[k], g_smear[(size_t)k * S_PTS + s], res);
        }
    }
    out[s] = env * res;
}

// ---------------- launch ------------------------------------------------------
extern "C" void kernel_launch(void* const* d_in, const int* in_sizes, int n_in,
                              void* d_out, int out_size) {
    const float* x     = (const float*)d_in[0];
    const float* sw    = (const float*)d_in[1];
    const float* kmean = (const float*)d_in[2];
    const float* klow  = (const float*)d_in[3];
    const float* khigh = (const float*)d_in[4];
    const float* emean = (const float*)d_in[5];
    const float* elow  = (const float*)d_in[6];
    const float* ehigh = (const float*)d_in[7];
    const float* pol   = (const float*)d_in[8];
    float* out = (float*)d_out;

    knot_one<<<NBLK, NTHR>>>(x, sw, kmean, klow, khigh, emean, elow, ehigh, pol, out);
}

// round 9
// speedup vs baseline: 5.3671x; 1.0048x over previous
#include <cuda_runtime.h>
#include <math.h>

#define KNOTS   1024
#define S_PTS   4095
#define INV_SAMP (1.0f / 4096.0f)
#define INV_S    (1.0f / (float)S_PTS)
#define NMOM   7            // Taylor n = 0..6 (gate 0.1 -> err <= 2e-11/knot)
#define GATE   0.1f
#define NBLK   8
#define NTHR   512
#define TGUARD 13.3f        // conservative: e<88 <=> |a|<13.2665

// ---------------- scratch (device globals; slow path only) -------------------
__device__ float g_smear[(size_t)KNOTS * S_PTS];
__device__ float g_rowsum[KNOTS], g_coef1[KNOTS];
__device__ float g_cwp[NBLK * KNOTS];
__device__ float g_Rp[NBLK];
__device__ unsigned g_count = 0;   // self-resetting per barrier episode
__device__ unsigned g_gen   = 0;   // monotone across graph replays

// ---------------- warp helpers -------------------------------------------------
__device__ __forceinline__ float warp_sum(float v) {
    #pragma unroll
    for (int o = 16; o > 0; o >>= 1) v += __shfl_xor_sync(0xFFFFFFFFu, v, o);
    return v;
}
__device__ __forceinline__ float warp_max(float v) {
    #pragma unroll
    for (int o = 16; o > 0; o >>= 1) v = fmaxf(v, __shfl_xor_sync(0xFFFFFFFFu, v, o));
    return v;
}
__device__ __forceinline__ float warp_min(float v) {
    #pragma unroll
    for (int o = 16; o > 0; o >>= 1) v = fminf(v, __shfl_xor_sync(0xFFFFFFFFu, v, o));
    return v;
}
// broadcast block sum for the slow path (512 threads = 16 warps)
__device__ __forceinline__ float block_sum_b(float v, float* red) {
    int tid = threadIdx.x;
    v = warp_sum(v);
    if ((tid & 31) == 0) red[tid >> 5] = v;
    __syncthreads();
    if (tid == 0) {
        float r = red[0];
        #pragma unroll
        for (int w = 1; w < NTHR / 32; w++) r += red[w];
        red[16] = r;
    }
    __syncthreads();
    float o = red[16];
    __syncthreads();
    return o;
}

// ---------------- software grid barrier (slow path only) ---------------------
__device__ __forceinline__ void grid_barrier() {
    __threadfence();
    __syncthreads();
    if (threadIdx.x == 0) {
        unsigned my = *((volatile unsigned*)&g_gen);
        if (atomicAdd(&g_count, 1u) == NBLK - 1) {
            g_count = 0;
            __threadfence();
            *((volatile unsigned*)&g_gen) = my + 1;
        } else {
            while (*((volatile unsigned*)&g_gen) == my) { }
        }
        __threadfence();
    }
    __syncthreads();
}

// ======================= the single kernel ====================================
__global__ __launch_bounds__(NTHR, 1)
void knot_one(const float* __restrict__ x,
              const float* __restrict__ sw,
              const float* __restrict__ kmean,
              const float* __restrict__ klow,
              const float* __restrict__ khigh,
              const float* __restrict__ emean,
              const float* __restrict__ elow,
              const float* __restrict__ ehigh,
              const float* __restrict__ pol,
              float* __restrict__ out) {
    // pool (36 KB) aliased per phase:
    //   fast reduce:  buf[16 * 512]          (32 KB)
    //   slow mix:     9 arrays x 1024        (36 KB)
    //   slow output:  6 arrays x 1024        (24 KB)
    __shared__ float pool[9216];
    __shared__ float red[17];
    __shared__ float s_res[16];
    __shared__ float s_cf[2 * NMOM];
    __shared__ int   s_fastenv;

    const int tid  = threadIdx.x;
    const int bid  = blockIdx.x;
    const int warp = tid >> 5, lane = tid & 31;

    // =============== phase 1: vectorized loads, 2 knots/thread ===============
    const float2 swv  = *(const float2*)sw;
    const float lower = swv.x, upper = swv.y;
    const float2 xk2  = ((const float2*)x)[tid];
    const float2 kml2 = ((const float2*)klow)[tid];
    const float2 kmh2 = ((const float2*)khigh)[tid];
    const float2 kmn2 = ((const float2*)kmean)[tid];
    const float2 eml2 = ((const float2*)emean)[tid];
    const float2 eln2 = ((const float2*)elow)[tid];
    const float2 ehn2 = ((const float2*)ehigh)[tid];

    float B2[2], v0c2[2], clo2[2], chi2[2], em2[2], eel2[2], eeh2[2];
    int noncst = 0;
    #pragma unroll
    for (int q = 0; q < 2; q++) {
        float xk   = q ? xk2.y  : xk2.x;
        float kml  = q ? kml2.y : kml2.x;
        float kmh  = q ? kmh2.y : kmh2.x;
        float mean = q ? kmn2.y : kmn2.x;
        float xlow  = (1.0f - lower) * xk;
        float xstep = ((upper - lower) * xk) * INV_SAMP;
        int   cst   = (xstep == 0.0f) ? 1 : 0;
        float rl = __expf(-kml);
        float rh = __expf(-kmh);
        float d  = xlow - mean;
        float r0 = (xlow <= mean) ? rl : rh;
        float a0 = d * r0;
        float v0 = __expf(-0.5f * a0 * a0);
        float B  = (float)S_PTS * v0;
        B2[q]   = B;
        v0c2[q] = cst ? v0 : 0.0f;
        if (!cst) noncst = 1;

        float highs = (1.0f + upper) * xk;
        float erlw = __expf(-xlow);
        float erhg = __expf(-highs);
        float hlo = xk * erlw, hhi = xk * erhg;
        clo2[q] = 0.5f * hlo * hlo;
        chi2[q] = 0.5f * hhi * hhi;

        em2[q]  = q ? eml2.y : eml2.x;
        eel2[q] = __expf(q ? eln2.y : eln2.x);  // TGUARD/exp(-elow) == TGUARD*exp(elow)
        eeh2[q] = __expf(q ? ehn2.y : ehn2.x);
    }

    // =============== phase 2: single batched 16-quantity reduction ===========
    {
        float* buf = pool;
        float pl0 = clo2[0], pl1 = clo2[1], ph0 = chi2[0], ph1 = chi2[1];
        #pragma unroll
        for (int n = 1; n <= 6; n++) {
            buf[(n - 1) * NTHR + tid] = pl0 + pl1;       // q 0..5 : low moments
            buf[(5 + n) * NTHR + tid] = ph0 + ph1;       // q 6..11: high moments
            pl0 *= clo2[0]; pl1 *= clo2[1];
            ph0 *= chi2[0]; ph1 *= chi2[1];
        }
        buf[12 * NTHR + tid] = v0c2[0] + v0c2[1];                          // v0 sum
        buf[13 * NTHR + tid] = fmaxf(fmaxf(clo2[0], chi2[0]),
                                     fmaxf(clo2[1], chi2[1]));             // cmax
        buf[14 * NTHR + tid] = fminf(B2[0], B2[1]);                        // Bmin
        buf[15 * NTHR + tid] = fmaxf(B2[0], B2[1]);                        // Bmax
    }
    int anyvar = __syncthreads_or(noncst);   // barrier #1 (covers buf writes)

    {
        const float* b = pool + warp * NTHR;
        float a0 = b[lane], a1 = b[lane + 32], a2 = b[lane + 64], a3 = b[lane + 96];
        float a4 = b[lane + 128], a5 = b[lane + 160], a6 = b[lane + 192], a7 = b[lane + 224];
        float a8 = b[lane + 256], a9 = b[lane + 288], aA = b[lane + 320], aB = b[lane + 352];
        float aC = b[lane + 384], aD = b[lane + 416], aE = b[lane + 448], aF = b[lane + 480];
        float v;
        if (warp == 13 || warp == 15) {       // max
            v = fmaxf(fmaxf(fmaxf(a0, a1), fmaxf(a2, a3)),
                      fmaxf(fmaxf(a4, a5), fmaxf(a6, a7)));
            v = fmaxf(v, fmaxf(fmaxf(fmaxf(a8, a9), fmaxf(aA, aB)),
                               fmaxf(fmaxf(aC, aD), fmaxf(aE, aF))));
            v = warp_max(v);
        } else if (warp == 14) {              // min
            v = fminf(fminf(fminf(a0, a1), fminf(a2, a3)),
                      fminf(fminf(a4, a5), fminf(a6, a7)));
            v = fminf(v, fminf(fminf(fminf(a8, a9), fminf(aA, aB)),
                               fminf(fminf(aC, aD), fminf(aE, aF))));
            v = warp_min(v);
        } else {                              // sum
            v = ((a0 + a1) + (a2 + a3)) + ((a4 + a5) + (a6 + a7))
              + ((a8 + a9) + (aA + aB)) + ((aC + aD) + (aE + aF));
            v = warp_sum(v);
        }
        if (lane == 0) s_res[warp] = v;
    }
    __syncthreads();                          // barrier #2 (s_res visible)

    // =============== phase 3: pass test + coefficients, one or-barrier =======
    const float Bmin = s_res[14], Bmax = s_res[15];
    int pass = 0;
    #pragma unroll
    for (int q = 0; q < 2; q++) {
        float lo = em2[q] - TGUARD * eel2[q];
        float hi = em2[q] + TGUARD * eeh2[q];
        float cminj = Bmin * B2[q] * INV_S;
        float cmaxj = Bmax * B2[q] * INV_S;
        // NaN-safe: NaN comparisons are false -> pass=1 -> slow path
        if (!(cmaxj < lo) && !(cminj > hi)) pass = 1;
    }

    if (tid < 2 * NMOM) {
        const float invfact[NMOM] = {1.0f, 1.0f, 0.5f, 1.0f/6.0f, 1.0f/24.0f,
                                     1.0f/120.0f, 1.0f/720.0f};
        int side = (tid >= NMOM) ? 1 : 0;
        int n    = tid - side * NMOM;
        s_cf[tid] = (n == 0) ? (float)KNOTS
                             : s_res[side * 6 + (n - 1)] * invfact[n];
        if (tid == 0) {
            float phi0 = -lower;
            float phiE = fmaf((float)(S_PTS - 1) * INV_SAMP, lower + upper, -lower);
            float tmax = fmaxf(phi0 * phi0, phiE * phiE);
            float gate = s_res[13] * tmax;
            s_fastenv = (gate <= GATE) ? 1 : 0;   // NaN -> slow env loop
        }
    }
    float R = (float)(KNOTS - 1) * s_res[12];      // Rbase
    // barrier #3: or-result + visibility of s_cf / s_fastenv
    const int slow = __syncthreads_or(pass) | anyvar;

    // ======================= SLOW PATH (general correctness) =================
    float* s_w    = pool;
    float* s_glow = pool + 1024;
    float* s_gd   = pool + 2048;
    float* s_grl  = pool + 3072;
    float* s_grh  = pool + 4096;
    float* s_cst  = pool + 5120;

    if (slow) {
        float* sA   = pool;
        float* sB   = pool + 1024;
        float* sV0c = pool + 2048;
        float* sSvj = pool + 3072;
        float* sCb  = pool + 4096;
        float* sEm  = pool + 5120;
        float* sErl = pool + 6144;
        float* sErh = pool + 7168;
        float* sCw  = pool + 8192;

        const float2 pol2 = ((const float2*)pol)[tid];
        #pragma unroll
        for (int q = 0; q < 2; q++) {
            int k = 2 * tid + q;
            float sp, cp;
            __sincosf(q ? pol2.y : pol2.x, &sp, &cp);
            sA[k]   = B2[q];
            sB[k]   = B2[q];
            sV0c[k] = v0c2[q];
            sSvj[k] = sp * v0c2[q];
            sCb[k]  = cp * B2[q];
            sEm[k]  = em2[q];
            sErl[k] = 1.0f / eel2[q];   // exp(-elow)
            sErh[k] = 1.0f / eeh2[q];   // exp(-ehigh)
            sCw[k]  = 0.0f;
        }
        __syncthreads();

        // non-constant knots: true A via S-loop; owning block stores smear rows
        if (anyvar) {
            for (int k = 0; k < KNOTS; k++) {
                float xk = x[k];
                float xstep = ((upper - lower) * xk) * INV_SAMP;
                if (xstep == 0.0f) continue;
                float xlow = (1.0f - lower) * xk;
                float rl = __expf(-klow[k]);
                float rh = __expf(-khigh[k]);
                float mean = kmean[k];
                bool own = (bid == (k >> 7));    // 128 knots per owning block
                float* __restrict__ row = &g_smear[(size_t)k * S_PTS];
                float acc = 0.0f;
                for (int s = tid; s < S_PTS; s += NTHR) {
                    float gv = fmaf(xstep, (float)s, xlow);
                    float dd = gv - mean;
                    float rr = (gv <= mean) ? rl : rh;
                    float aa = dd * rr;
                    float vv = __expf(-0.5f * aa * aa);
                    if (own) row[s] = vv;
                    acc += vv;
                }
                float tot = block_sum_b(acc, red);
                if (tid == 0) sA[k] = tot;
                __syncthreads();
            }
        }

        // mix: 128 rows/block = 16 warps x 8 rows
        float rp = 0.0f;
        #pragma unroll
        for (int rr = 0; rr < 8; rr++) {
            int i = bid * 128 + rr * 16 + warp;
            float AiS  = sA[i] * INV_S;
            float Bi   = sB[i];
            float v0ci = sV0c[i];
            float rs = 0.0f, c1 = 0.0f;
            for (int j = lane; j < KNOTS; j += 32) {
                float corr = AiS * sA[j];
                float em = sEm[j];
                float dd = corr - em;
                float r  = (corr <= em) ? sErl[j] : sErh[j];
                float a  = dd * r;
                float e  = 0.5f * a * a;
                if (e < 88.0f) {
                    float m = __expf(-e);
                    if (j == i) m = 0.0f;
                    float cb = sCb[j];
                    rs += m;
                    c1 += m * cb;
                    rp += m * (v0ci * (cb - 1.0f) + Bi * sSvj[j]);
                    float v = Bi * m;
                    if (v != 0.0f) atomicAdd(&sCw[j], v);
                }
            }
            rs = warp_sum(rs);
            c1 = warp_sum(c1);
            if (lane == 0) { g_rowsum[i] = rs; g_coef1[i] = c1; }
        }
        float rpt = block_sum_b(rp, red);
        if (tid == 0) g_Rp[bid] = rpt;
        __syncthreads();
        #pragma unroll
        for (int q = 0; q < 2; q++) {
            int k = 2 * tid + q;
            g_cwp[bid * KNOTS + k] = sCw[k];
        }

        grid_barrier();

        #pragma unroll
        for (int p = 0; p < NBLK; p++) R += g_Rp[p];

        __syncthreads();
        #pragma unroll
        for (int q = 0; q < 2; q++) {
            int k = 2 * tid + q;
            float xk = x[k];
            float xlow  = (1.0f - lower) * xk;
            float xstep = ((upper - lower) * xk) * INV_SAMP;
            float cw = 0.0f;
            #pragma unroll
            for (int p = 0; p < NBLK; p++) cw += g_cwp[p * KNOTS + k];
            float w = g_coef1[k] + (float)(KNOTS - 1) - g_rowsum[k]
                    + __sinf(pol[k]) * cw;
            float highs = (1.0f + upper) * xk;
            s_w[k]    = w;
            s_cst[k]  = (xstep == 0.0f) ? 1.0f : 0.0f;
            s_glow[k] = xlow;
            s_gd[k]   = highs - xlow;
            s_grl[k]  = __expf(-xlow);
            s_grh[k]  = __expf(-highs);
        }
        __syncthreads();
    } else if (!s_fastenv) {
        // fast path but envelope needs the exact per-knot loop
        __syncthreads();   // buf dead
        #pragma unroll
        for (int q = 0; q < 2; q++) {
            int k = 2 * tid + q;
            float xk = (q ? xk2.y : xk2.x);
            float xlow  = (1.0f - lower) * xk;
            float highs = (1.0f + upper) * xk;
            s_glow[k] = xlow;
            s_gd[k]   = highs - xlow;
            s_grl[k]  = __expf(-xlow);
            s_grh[k]  = __expf(-highs);
        }
        __syncthreads();
    }

    // ======================= output (1 sample / thread) ======================
    int s = bid * NTHR + tid;
    if (s >= S_PTS) return;

    float xi  = (float)s * INV_SAMP;
    float phi = fmaf(xi, lower + upper, -lower);
    float t   = phi * phi;

    float env;
    if (s_fastenv) {
        const float* cf = s_cf + ((phi <= 0.0f) ? 0 : NMOM);
        float u = -t;
        env = cf[NMOM - 1];
        #pragma unroll
        for (int n = NMOM - 2; n >= 0; n--) env = fmaf(env, u, cf[n]);
    } else {
        env = 0.0f;
        for (int k = 0; k < KNOTS; k++) {
            float mean = x[k];
            float gv = fmaf(s_gd[k], xi, s_glow[k]);
            float dd = gv - mean;
            float r  = (gv <= mean) ? s_grl[k] : s_grh[k];
            float a  = dd * r;
            env += __expf(-0.5f * a * a);
        }
    }

    float res = R;
    if (slow && anyvar) {
        for (int k = 0; k < KNOTS; k++) {
            if (s_cst[k] == 0.0f)
                res = fmaf(s_w[k], g_smear[(size_t)k * S_PTS + s], res);
        }
    }
    out[s] = env * res;
}

// ---------------- launch ------------------------------------------------------
extern "C" void kernel_launch(void* const* d_in, const int* in_sizes, int n_in,
                              void* d_out, int out_size) {
    const float* x     = (const float*)d_in[0];
    const float* sw    = (const float*)d_in[1];
    const float* kmean = (const float*)d_in[2];
    const float* klow  = (const float*)d_in[3];
    const float* khigh = (const float*)d_in[4];
    const float* emean = (const float*)d_in[5];
    const float* elow  = (const float*)d_in[6];
    const float* ehigh = (const float*)d_in[7];
    const float* pol   = (const float*)d_in[8];
    float* out = (float*)d_out;

    knot_one<<<NBLK, NTHR>>>(x, sw, kmean, klow, khigh, emean, elow, ehigh, pol, out);
}